// round 3
// baseline (speedup 1.0000x reference)
#include <cuda_runtime.h>

#define D      1024
#define NCOL   20000
#define TWO_M  512
#define DM1    1023
#define BLK    128
#define NBLK   157
#define FETA   1e-5f
#define EPS    (2.0f * FETA)
#define NCTA_TOT 9
#define NCTA_W   8
#define NTH    512
#define NAPP   6
#define XSTR   132          // padded row stride for X tiles (floats)
#define SSTR   129          // padded row stride for S (floats)
#define DSMF   (2 * BLK * XSTR + BLK * SSTR)   // 50304 floats = 201216 B

// ---------------- device globals (no allocation allowed) ----------------
__device__ __align__(16) float g_Sall[(size_t)NBLK * BLK * BLK];  // 10.3 MB
__device__ float g_dpart[NCTA_W][2][2][BLK];  // [cta][d/e][half][col]
__device__ float g_sgc[2][BLK];               // [0]=sg, [1]=c (current block)
__device__ float g_x0[D];
__device__ float g_T0, g_q0;
__device__ int g_barc;
__device__ volatile int g_bare;

// ---------------- init ----------------
__global__ __launch_bounds__(1024) void init_kernel(const float* __restrict__ At,
                                                    const float* __restrict__ w1) {
    __shared__ float red[32];
    int tid = threadIdx.x;
    float x0 = At[(size_t)tid * NCOL];
    g_x0[tid] = x0;
    float p = w1[tid] * x0;
    #pragma unroll
    for (int o = 16; o; o >>= 1) p += __shfl_down_sync(0xffffffffu, p, o);
    if ((tid & 31) == 0) red[tid >> 5] = p;
    __syncthreads();
    if (tid < 32) {
        float q = red[tid];
        #pragma unroll
        for (int o = 16; o; o >>= 1) q += __shfl_down_sync(0xffffffffu, q, o);
        if (tid == 0) { g_q0 = q; g_barc = 0; g_bare = 0; }
    }
    // zero dpart (8*2*2*128 = 4096 floats)
    float* dp = &g_dpart[0][0][0][0];
    #pragma unroll
    for (int i = 0; i < 4; i++) dp[tid + 1024 * i] = 0.0f;
}

// ---------------- T0 = ||W2_init @ a_0||^2, single block (deterministic) ----------------
__global__ __launch_bounds__(1024) void t0_kernel(const float* __restrict__ W2) {
    __shared__ float part[32];
    int w = threadIdx.x >> 5, lane = threadIdx.x & 31;
    float acc = 0.0f;
    for (int m = w; m < TWO_M; m += 32) {
        const float* row = W2 + (size_t)m * DM1;
        float p = 0.0f;
        for (int c = lane; c < DM1; c += 32) p = fmaf(row[c], g_x0[c], p);
        #pragma unroll
        for (int o = 16; o; o >>= 1) p += __shfl_down_sync(0xffffffffu, p, o);
        if (lane == 0) acc = fmaf(p, p, acc);
    }
    if (lane == 0) part[w] = acc;
    __syncthreads();
    if (threadIdx.x < 32) {
        float v = part[threadIdx.x];
        #pragma unroll
        for (int o = 16; o; o >>= 1) v += __shfl_down_sync(0xffffffffu, v, o);
        if (threadIdx.x == 0) g_T0 = v;
    }
}

// ---------------- copy b into out[N..2N) ----------------
__global__ void copyb_kernel(const float* __restrict__ b, float* __restrict__ out) {
    int i = blockIdx.x * blockDim.x + threadIdx.x;
    if (i < NCOL) out[NCOL + i] = b[i];
}

// ---------------- ALL diag Gram blocks; grid=157, no atomics ----------------
__global__ __launch_bounds__(256) void gram_all_kernel(const float* __restrict__ At) {
    __shared__ float sh[32][BLK];
    int k = blockIdx.x, s = k * BLK, tid = threadIdx.x;
    int ty = tid >> 4, tx = tid & 15;
    float acc[8][8];
    #pragma unroll
    for (int i = 0; i < 8; i++)
        #pragma unroll
        for (int j = 0; j < 8; j++) acc[i][j] = 0.0f;

    for (int kt = 0; kt < 32; kt++) {
        int r0 = kt * 32;
        #pragma unroll
        for (int i = 0; i < 4; i++) {
            int f = tid + 256 * i;           // 1024 float4
            int r = f >> 5;
            int c4 = (f & 31) * 4;
            float4 v = make_float4(0.f, 0.f, 0.f, 0.f);
            if (s + c4 + 3 < NCOL)
                v = *(const float4*)(At + (size_t)(r0 + r) * NCOL + s + c4);
            *(float4*)&sh[r][c4] = v;
        }
        __syncthreads();
        #pragma unroll 4
        for (int r2 = 0; r2 < 32; r2++) {
            float4 a4 = *(const float4*)&sh[r2][8 * ty];
            float4 a5 = *(const float4*)&sh[r2][8 * ty + 4];
            float4 b4 = *(const float4*)&sh[r2][8 * tx];
            float4 b5 = *(const float4*)&sh[r2][8 * tx + 4];
            float av[8] = {a4.x,a4.y,a4.z,a4.w,a5.x,a5.y,a5.z,a5.w};
            float bv[8] = {b4.x,b4.y,b4.z,b4.w,b5.x,b5.y,b5.z,b5.w};
            #pragma unroll
            for (int i = 0; i < 8; i++)
                #pragma unroll
                for (int j = 0; j < 8; j++) acc[i][j] = fmaf(av[i], bv[j], acc[i][j]);
        }
        __syncthreads();
    }
    float* Sk = g_Sall + (size_t)k * BLK * BLK;
    #pragma unroll
    for (int i = 0; i < 8; i++)
        #pragma unroll
        for (int j = 0; j < 8; j++)
            Sk[(8 * ty + i) * BLK + (8 * tx + j)] = acc[i][j];
}

// ---------------- grid barrier (9 co-resident CTAs) ----------------
__device__ __forceinline__ void gridbar() {
    __threadfence();
    __syncthreads();
    if (threadIdx.x == 0) {
        int e = g_bare;
        if (atomicAdd(&g_barc, 1) == NCTA_TOT - 1) {
            atomicExch(&g_barc, 0);
            __threadfence();
            g_bare = e + 1;
        } else {
            while (g_bare == e) { }
        }
    }
    __syncthreads();
}

// ---------------- persistent loop kernel ----------------
__device__ __forceinline__ void stageX(float* dst, const float* __restrict__ At,
                                       int s, int cta, int tid) {
    int rb = (cta - 1) * BLK;
    #pragma unroll
    for (int i = 0; i < 8; i++) {
        int f = tid + NTH * i;           // 0..4095
        int r = f >> 5;
        int c4 = (f & 31) * 4;
        float4 v = make_float4(0.f, 0.f, 0.f, 0.f);
        if (s + c4 + 3 < NCOL)
            v = *(const float4*)(At + (size_t)(rb + r) * NCOL + s + c4);
        *(float4*)&dst[r * XSTR + c4] = v;
    }
}

__device__ __forceinline__ void stageS(float* Ssm, int kk, int tid) {
    const float* src = g_Sall + (size_t)kk * BLK * BLK;
    #pragma unroll
    for (int i = 0; i < 32; i++) {
        int e = tid + NTH * i;           // 0..16383
        Ssm[(e >> 7) * SSTR + (e & 127)] = src[e];
    }
}

__global__ __launch_bounds__(NTH) void persist_kernel(const float* __restrict__ At,
                                                      const float* __restrict__ b,
                                                      float* __restrict__ out) {
    extern __shared__ float dsm[];
    float* Xb0 = dsm;
    float* Xb1 = dsm + BLK * XSTR;
    float* Ssm = dsm + 2 * BLK * XSTR;

    __shared__ float gws[BLK], vs[BLK], shsg[BLK], shc[BLK];
    __shared__ float s_dd[BLK], s_rhs[BLK], s_ya[BLK], s_yb[BLK];
    __shared__ float s_z[BLK], s_bb[BLK], s_tq[BLK], s_pref[BLK];
    __shared__ float s_mv[2][BLK], s_cc[BLK];

    const int tid = threadIdx.x;
    const int cta = blockIdx.x;
    const int rl = tid >> 2, q = tid & 3;
    const int row = (cta - 1) * BLK + rl;
    const float T0 = g_T0;
    const float q0 = g_q0;
    float gw1 = 0.0f, vv = 0.0f;

    // ---------- solver routine (CTA 0), Ssm already staged ----------
    auto solve = [&](int kk) {
        int s = kk * BLK;
        int n = NCOL - s; if (n > BLK) n = BLK;
        if (tid < BLK) {
            int gi = s + tid;
            float dsum = 0.f, esum = 0.f;
            #pragma unroll
            for (int c2 = 0; c2 < NCTA_W; c2++) {
                dsum += __ldcv(&g_dpart[c2][0][0][tid]) + __ldcv(&g_dpart[c2][0][1][tid]);
                esum += __ldcv(&g_dpart[c2][1][0][tid]) + __ldcv(&g_dpart[c2][1][1][tid]);
            }
            s_dd[tid] = dsum;
            float pe = -EPS * esum;
            if (kk == 0 && tid == 0) pe = 1.0f;     // forces c_0 = 1
            s_rhs[tid] = pe; s_ya[tid] = pe;
            s_z[tid]  = (gi < NCOL) ? At[(size_t)DM1 * NCOL + gi] : 0.f;
            s_bb[tid] = (gi < NCOL) ? b[gi] : 0.f;
        }
        __syncthreads();
        // --- c chain: Neumann, G = S - z z^T ---
        float* yc = s_ya; float* yn = s_yb;
        for (int it = 0; it < NAPP; it++) {
            if (tid < BLK) s_tq[tid] = s_z[tid] * yc[tid];
            __syncthreads();
            if (tid < 32) {            // exclusive prefix of tq
                float v0 = s_tq[4*tid], v1 = s_tq[4*tid+1], v2 = s_tq[4*tid+2], v3 = s_tq[4*tid+3];
                float i0 = v0, i1 = i0+v1, i2 = i1+v2, i3 = i2+v3;
                float run = i3;
                #pragma unroll
                for (int o = 1; o < 32; o <<= 1) {
                    float u = __shfl_up_sync(0xffffffffu, run, o);
                    if ((int)tid >= o) run += u;
                }
                float ex = run - i3;
                s_pref[4*tid] = ex; s_pref[4*tid+1] = ex+i0;
                s_pref[4*tid+2] = ex+i1; s_pref[4*tid+3] = ex+i2;
            }
            if (tid >= 128 && tid < 384) {          // matvec with strict lower S^T
                int t2 = tid - 128;
                int i = t2 & 127, h = t2 >> 7;
                int jb = h * 64;
                int je = h ? i : (i < 64 ? i : 64);
                float a0 = 0.f, a1 = 0.f;
                int j = jb;
                for (; j + 1 < je; j += 2) {
                    a0 = fmaf(Ssm[j * SSTR + i],       yc[j],     a0);
                    a1 = fmaf(Ssm[(j + 1) * SSTR + i], yc[j + 1], a1);
                }
                if (j < je) a0 = fmaf(Ssm[j * SSTR + i], yc[j], a0);
                s_mv[h][i] = a0 + a1;
            }
            __syncthreads();
            if (tid < BLK) {
                float m = s_mv[0][tid] + s_mv[1][tid] - s_z[tid] * s_pref[tid];
                yn[tid] = fmaf(-EPS, m, s_rhs[tid]);
            }
            __syncthreads();
            float* t = yc; yc = yn; yn = t;
        }
        if (tid < BLK) {
            float c = yc[tid];
            s_cc[tid] = c;
            float r = fmaf(-EPS, s_dd[tid], fmaf(2.0f * T0, c * c, -2.0f * s_bb[tid]));
            if (kk == 0 && tid == 0) r += 2.0f * q0;
            s_rhs[tid] = r;
            s_ya[tid] = r;
        }
        __syncthreads();
        // --- sg chain: Neumann with S only ---
        yc = s_ya; yn = s_yb;
        for (int it = 0; it < NAPP; it++) {
            if (tid >= 128 && tid < 384) {
                int t2 = tid - 128;
                int i = t2 & 127, h = t2 >> 7;
                int jb = h * 64;
                int je = h ? i : (i < 64 ? i : 64);
                float a0 = 0.f, a1 = 0.f;
                int j = jb;
                for (; j + 1 < je; j += 2) {
                    a0 = fmaf(Ssm[j * SSTR + i],       yc[j],     a0);
                    a1 = fmaf(Ssm[(j + 1) * SSTR + i], yc[j + 1], a1);
                }
                if (j < je) a0 = fmaf(Ssm[j * SSTR + i], yc[j], a0);
                s_mv[h][i] = a0 + a1;
            }
            __syncthreads();
            if (tid < BLK) {
                float m = s_mv[0][tid] + s_mv[1][tid];
                yn[tid] = fmaf(-EPS, m, s_rhs[tid]);
            }
            __syncthreads();
            float* t = yc; yc = yn; yn = t;
        }
        if (tid < BLK) {
            float sg = yc[tid];
            g_sgc[0][tid] = sg;
            g_sgc[1][tid] = s_cc[tid];
            if (tid < n) out[s + tid] = fmaf(0.5f, sg, s_bb[tid]);
        }
    };

    // ---------- prologue ----------
    if (cta == 0) {
        stageS(Ssm, 0, tid);
        __syncthreads();
        solve(0);
    } else {
        stageX(Xb0, At, 0, cta, tid);
        stageX(Xb1, At, BLK, cta, tid);
    }
    gridbar();

    // ---------- main loop ----------
    for (int k = 0; k < NBLK - 1; k++) {
        float* Xc = (k & 1) ? Xb1 : Xb0;
        float* Xn = (k & 1) ? Xb0 : Xb1;
        // --- phase A ---
        if (cta == 0) {
            stageS(Ssm, k + 1, tid);
        } else {
            if (tid < BLK) {
                shsg[tid] = __ldcv(&g_sgc[0][tid]);
                shc[tid]  = __ldcv(&g_sgc[1][tid]);
            }
            __syncthreads();
            // update owned gw1/v rows with block k
            const float4* xr = (const float4*)(Xc + rl * XSTR);
            float w = 0.f, u = 0.f;
            #pragma unroll
            for (int i2 = 0; i2 < 8; i2++) {
                float4 x = xr[q * 8 + i2];
                int ib = q * 32 + i2 * 4;
                w = fmaf(shsg[ib+0], x.x, w); u = fmaf(shc[ib+0], x.x, u);
                w = fmaf(shsg[ib+1], x.y, w); u = fmaf(shc[ib+1], x.y, u);
                w = fmaf(shsg[ib+2], x.z, w); u = fmaf(shc[ib+2], x.z, u);
                w = fmaf(shsg[ib+3], x.w, w); u = fmaf(shc[ib+3], x.w, u);
            }
            w += __shfl_xor_sync(0xffffffffu, w, 1); w += __shfl_xor_sync(0xffffffffu, w, 2);
            u += __shfl_xor_sync(0xffffffffu, u, 1); u += __shfl_xor_sync(0xffffffffu, u, 2);
            gw1 += w; vv += u;
            if (q == 0) { gws[rl] = gw1; vs[rl] = (row == DM1) ? 0.f : vv; }
            __syncthreads();
            // far dots for block k+1
            int ch = tid >> 8;
            int hh = (tid >> 7) & 1;
            int ii = tid & 127;
            const float* wv = ch ? vs : gws;
            float a0 = 0.f, a1 = 0.f;
            int rb2 = hh * 64;
            #pragma unroll 8
            for (int r = 0; r < 64; r += 2) {
                a0 = fmaf(wv[rb2 + r],     Xn[(rb2 + r)     * XSTR + ii], a0);
                a1 = fmaf(wv[rb2 + r + 1], Xn[(rb2 + r + 1) * XSTR + ii], a1);
            }
            g_dpart[cta - 1][ch][hh][ii] = a0 + a1;
        }
        gridbar();
        // --- phase B ---
        if (cta == 0) {
            solve(k + 1);
        } else {
            if (k + 2 < NBLK) stageX(Xc, At, (k + 2) * BLK, cta, tid);
        }
        gridbar();
    }
}

// ---------------- launch ----------------
extern "C" void kernel_launch(void* const* d_in, const int* in_sizes, int n_in,
                              void* d_out, int out_size) {
    const float* At = (const float*)d_in[0];
    const float* b  = (const float*)d_in[1];
    const float* w1 = (const float*)d_in[2];
    const float* W2 = (const float*)d_in[3];
    float* out = (float*)d_out;

    cudaFuncSetAttribute(persist_kernel, cudaFuncAttributeMaxDynamicSharedMemorySize,
                         DSMF * (int)sizeof(float));

    init_kernel<<<1, 1024>>>(At, w1);
    t0_kernel<<<1, 1024>>>(W2);
    if (out_size >= 2 * NCOL)
        copyb_kernel<<<(NCOL + 255) / 256, 256>>>(b, out);
    gram_all_kernel<<<NBLK, 256>>>(At);
    persist_kernel<<<NCTA_TOT, NTH, DSMF * sizeof(float)>>>(At, b, out);
}

// round 4
// speedup vs baseline: 1.5935x; 1.5935x over previous
#include <cuda_runtime.h>

#define D      1024
#define NCOL   20000
#define TWO_M  512
#define DM1    1023
#define BLK    128
#define NBLK   157
#define FETA   1e-5f
#define EPS    (2.0f * FETA)
#define NIT    18
#define XS_STR 132
#define BIGSM  (2 * 128 * XS_STR * (int)sizeof(float))   // 135168 B

// ---------------- device globals (no allocation allowed) ----------------
__device__ __align__(16) float g_Spart[2][(size_t)NBLK * BLK * BLK]; // gram K-half partials
__device__ __align__(16) float g_Sall[(size_t)NBLK * BLK * BLK];     // merged local Grams
__device__ __align__(16) float g_u[2][NBLK][D];    // per-block u = X y  (0=c, 1=sg)
__device__ __align__(16) float g_U[2][NBLK][D];    // exclusive prefixes of u
__device__ float g_pz[NBLK], g_Pz[NBLK];           // z-weighted block sums + prefix
__device__ __align__(16) float g_y[2][NBLK * BLK]; // current iterates (c, sg)
__device__ float g_x0[D];
__device__ float g_T0, g_q0;

// ---------------- init: x0 gather, q0 = w1.x0, zero T0 ----------------
__global__ __launch_bounds__(1024) void init_kernel(const float* __restrict__ At,
                                                    const float* __restrict__ w1) {
    __shared__ float red[32];
    int tid = threadIdx.x;
    float x0 = At[(size_t)tid * NCOL];
    g_x0[tid] = x0;
    float p = w1[tid] * x0;
    #pragma unroll
    for (int o = 16; o; o >>= 1) p += __shfl_down_sync(0xffffffffu, p, o);
    if ((tid & 31) == 0) red[tid >> 5] = p;
    __syncthreads();
    if (tid < 32) {
        float q = red[tid];
        #pragma unroll
        for (int o = 16; o; o >>= 1) q += __shfl_down_sync(0xffffffffu, q, o);
        if (tid == 0) { g_q0 = q; g_T0 = 0.0f; }
    }
}

// ---------------- T0 = ||W2_init @ a_0||^2 ; grid 16 ----------------
__global__ __launch_bounds__(256) void t0_kernel(const float* __restrict__ W2) {
    int wid = threadIdx.x >> 5, lane = threadIdx.x & 31;
    float acc = 0.0f;
    #pragma unroll
    for (int rr = 0; rr < 4; rr++) {
        int m = blockIdx.x * 32 + wid * 4 + rr;
        const float* row = W2 + (size_t)m * DM1;
        float p = 0.0f;
        for (int c = lane; c < DM1; c += 32) p = fmaf(row[c], g_x0[c], p);
        #pragma unroll
        for (int o = 16; o; o >>= 1) p += __shfl_down_sync(0xffffffffu, p, o);
        if (lane == 0) acc = fmaf(p, p, acc);
    }
    if (lane == 0) atomicAdd(&g_T0, acc);
}

// ---------------- copy b into out[N..2N) ----------------
__global__ void copyb_kernel(const float* __restrict__ b, float* __restrict__ out) {
    int i = blockIdx.x * blockDim.x + threadIdx.x;
    if (i < NCOL) out[NCOL + i] = b[i];
}

// ---------------- zero iteration state ----------------
__global__ void zeroYU_kernel() {
    int idx = blockIdx.x * blockDim.x + threadIdx.x;
    int stride = gridDim.x * blockDim.x;
    float* U = &g_U[0][0][0];
    for (int i = idx; i < 2 * NBLK * D; i += stride) U[i] = 0.0f;
    float* y = &g_y[0][0];
    for (int i = idx; i < 2 * NBLK * BLK; i += stride) y[i] = 0.0f;
    if (idx < NBLK) { g_pz[idx] = 0.0f; g_Pz[idx] = 0.0f; }
}

// ---------------- diag Gram partials; grid (157,2), no atomics ----------------
__global__ __launch_bounds__(256) void gram_kernel(const float* __restrict__ At) {
    __shared__ float sh[32][BLK];
    int k = blockIdx.x, s = k * BLK, kh = blockIdx.y, tid = threadIdx.x;
    int ty = tid >> 4, tx = tid & 15;
    float acc[8][8];
    #pragma unroll
    for (int i = 0; i < 8; i++)
        #pragma unroll
        for (int j = 0; j < 8; j++) acc[i][j] = 0.0f;

    for (int kt = 0; kt < 16; kt++) {
        int r0 = kh * 512 + kt * 32;
        #pragma unroll
        for (int i = 0; i < 4; i++) {
            int f = tid + 256 * i;
            int r = f >> 5;
            int c4 = (f & 31) * 4;
            float4 v = make_float4(0.f, 0.f, 0.f, 0.f);
            if (s + c4 + 3 < NCOL)
                v = *(const float4*)(At + (size_t)(r0 + r) * NCOL + s + c4);
            *(float4*)&sh[r][c4] = v;
        }
        __syncthreads();
        #pragma unroll 4
        for (int r2 = 0; r2 < 32; r2++) {
            float4 a4 = *(const float4*)&sh[r2][8 * ty];
            float4 a5 = *(const float4*)&sh[r2][8 * ty + 4];
            float4 b4 = *(const float4*)&sh[r2][8 * tx];
            float4 b5 = *(const float4*)&sh[r2][8 * tx + 4];
            float av[8] = {a4.x,a4.y,a4.z,a4.w,a5.x,a5.y,a5.z,a5.w};
            float bv[8] = {b4.x,b4.y,b4.z,b4.w,b5.x,b5.y,b5.z,b5.w};
            #pragma unroll
            for (int i = 0; i < 8; i++)
                #pragma unroll
                for (int j = 0; j < 8; j++) acc[i][j] = fmaf(av[i], bv[j], acc[i][j]);
        }
        __syncthreads();
    }
    float* Sk = g_Spart[kh] + (size_t)k * BLK * BLK;
    #pragma unroll
    for (int i = 0; i < 8; i++)
        #pragma unroll
        for (int j = 0; j < 8; j++)
            Sk[(8 * ty + i) * BLK + (8 * tx + j)] = acc[i][j];
}

// ---------------- merge gram halves ----------------
__global__ void merge_kernel() {
    int i = blockIdx.x * blockDim.x + threadIdx.x;   // 2512*256 = 643072 float4 exactly
    float4 a = ((const float4*)g_Spart[0])[i];
    float4 b = ((const float4*)g_Spart[1])[i];
    ((float4*)g_Sall)[i] = make_float4(a.x + b.x, a.y + b.y, a.z + b.z, a.w + b.w);
}

// ---------------- one Jacobi/Neumann sweep: all 157 blocks in parallel ----------------
__global__ __launch_bounds__(512) void big_kernel(const float* __restrict__ At,
                                                  const float* __restrict__ b,
                                                  float* __restrict__ out, int last) {
    extern __shared__ float dsm[];                 // 2 X-chunk buffers, later S
    __shared__ float Ucm[D], Usm[D];
    __shared__ float pAc[16][BLK], pAs[16][BLK];
    __shared__ float plc[4][BLK], pls[4][BLK];
    __shared__ float yco[BLK], yso[BLK], ycn[BLK], ysn[BLK];
    __shared__ float zz[BLK], bb[BLK], tq[BLK], pref[BLK];

    const int tid = threadIdx.x;
    const int k = blockIdx.x;
    const int s = k * BLK;
    const int n = (NCOL - s < BLK) ? (NCOL - s) : BLK;
    const int n4 = n >> 2;

    #pragma unroll
    for (int i = 0; i < 2; i++) {
        Ucm[tid + 512 * i] = g_U[0][k][tid + 512 * i];
        Usm[tid + 512 * i] = g_U[1][k][tid + 512 * i];
    }
    if (tid < BLK) {
        yco[tid] = g_y[0][k * BLK + tid];
        yso[tid] = g_y[1][k * BLK + tid];
        zz[tid] = (tid < n) ? At[(size_t)DM1 * NCOL + s + tid] : 0.f;
        bb[tid] = (tid < n) ? b[s + tid] : 0.f;
    }
    __syncthreads();

    // ---- Phase A: coupling dots  (x_i . U)  double-buffered chunks ----
    const int q8 = tid >> 5;          // 0..15
    const int cg = (tid & 31) * 4;    // column base
    float4 vcA = make_float4(0.f,0.f,0.f,0.f), vsA = make_float4(0.f,0.f,0.f,0.f);
    float* buf0 = dsm;
    float* buf1 = dsm + 128 * XS_STR;

    float4 ld[8];
    #pragma unroll
    for (int ii = 0; ii < 8; ii++) {
        int f = tid + 512 * ii; int r = f >> 5, c4 = (f & 31) * 4;
        ld[ii] = (c4 < n) ? *(const float4*)(At + (size_t)r * NCOL + s + c4)
                          : make_float4(0.f,0.f,0.f,0.f);
    }
    #pragma unroll
    for (int ii = 0; ii < 8; ii++) {
        int f = tid + 512 * ii; int r = f >> 5, c4 = (f & 31) * 4;
        *(float4*)&buf0[r * XS_STR + c4] = ld[ii];
    }
    __syncthreads();

    for (int ch = 0; ch < 8; ch++) {
        float* cur = (ch & 1) ? buf1 : buf0;
        float* nxt = (ch & 1) ? buf0 : buf1;
        if (ch + 1 < 8) {
            int rb = (ch + 1) * 128;
            #pragma unroll
            for (int ii = 0; ii < 8; ii++) {
                int f = tid + 512 * ii; int r = f >> 5, c4 = (f & 31) * 4;
                ld[ii] = (c4 < n) ? *(const float4*)(At + (size_t)(rb + r) * NCOL + s + c4)
                                  : make_float4(0.f,0.f,0.f,0.f);
            }
        }
        #pragma unroll
        for (int r2 = 0; r2 < 8; r2++) {
            int rr = q8 * 8 + r2;
            float uc = Ucm[ch * 128 + rr], us = Usm[ch * 128 + rr];
            float4 xv = *(const float4*)&cur[rr * XS_STR + cg];
            vcA.x = fmaf(uc, xv.x, vcA.x); vcA.y = fmaf(uc, xv.y, vcA.y);
            vcA.z = fmaf(uc, xv.z, vcA.z); vcA.w = fmaf(uc, xv.w, vcA.w);
            vsA.x = fmaf(us, xv.x, vsA.x); vsA.y = fmaf(us, xv.y, vsA.y);
            vsA.z = fmaf(us, xv.z, vsA.z); vsA.w = fmaf(us, xv.w, vsA.w);
        }
        if (ch + 1 < 8) {
            __syncthreads();
            #pragma unroll
            for (int ii = 0; ii < 8; ii++) {
                int f = tid + 512 * ii; int r = f >> 5, c4 = (f & 31) * 4;
                *(float4*)&nxt[r * XS_STR + c4] = ld[ii];
            }
            __syncthreads();
        }
    }
    *(float4*)&pAc[q8][cg] = vcA;
    *(float4*)&pAs[q8][cg] = vsA;
    __syncthreads();

    // ---- stage local Gram S into dsm ----
    {
        const float4* Sg = (const float4*)(g_Sall + (size_t)k * BLK * BLK);
        float4* Ss = (float4*)dsm;
        #pragma unroll
        for (int ii = 0; ii < 8; ii++) Ss[tid + 512 * ii] = Sg[tid + 512 * ii];
    }
    if (tid < BLK) tq[tid] = zz[tid] * yco[tid];
    __syncthreads();

    // ---- local strict-lower matvecs (both chains) ----
    {
        const int qq = tid >> 7, i = tid & 127, jb = qq * 32;
        float lc = 0.f, ls = 0.f;
        #pragma unroll 8
        for (int j2 = 0; j2 < 32; j2++) {
            int j = jb + j2;
            if (j < i) {
                float sv = dsm[j * BLK + i];
                lc = fmaf(sv, yco[j], lc);
                ls = fmaf(sv, yso[j], ls);
            }
        }
        plc[qq][i] = lc; pls[qq][i] = ls;
    }
    if (tid < 32) {          // exclusive prefix of z*yc_old
        float v0 = tq[4*tid], v1 = tq[4*tid+1], v2 = tq[4*tid+2], v3 = tq[4*tid+3];
        float i0 = v0, i1 = i0 + v1, i2 = i1 + v2, i3 = i2 + v3;
        float run = i3;
        #pragma unroll
        for (int o = 1; o < 32; o <<= 1) {
            float u2 = __shfl_up_sync(0xffffffffu, run, o);
            if ((int)tid >= o) run += u2;
        }
        float ex = run - i3;
        pref[4*tid] = ex; pref[4*tid+1] = ex + i0;
        pref[4*tid+2] = ex + i1; pref[4*tid+3] = ex + i2;
    }
    __syncthreads();

    // ---- combine + Jacobi update ----
    if (tid < BLK) {
        const int i = tid;
        float cc = 0.f, cs = 0.f;
        #pragma unroll
        for (int p = 0; p < 16; p++) { cc += pAc[p][i]; cs += pAs[p][i]; }
        float lc = plc[0][i] + plc[1][i] + plc[2][i] + plc[3][i];
        float ls = pls[0][i] + pls[1][i] + pls[2][i] + pls[3][i];
        float zp = g_Pz[k] + pref[i];
        float rc = (s + i == 0) ? 1.0f : 0.0f;
        float cnew = rc - EPS * (cc + lc - zz[i] * zp);
        float rs = fmaf(2.0f * g_T0, cnew * cnew, -2.0f * bb[i]);
        if (s + i == 0) rs += 2.0f * g_q0;
        float snew = rs - EPS * (cs + ls);
        ycn[i] = cnew; ysn[i] = snew;
        g_y[0][k * BLK + i] = cnew;
        g_y[1][k * BLK + i] = snew;
        if (last && i < n) out[s + i] = fmaf(0.5f, snew, bb[i]);
        tq[i] = zz[i] * cnew;
    }
    __syncthreads();
    if (tid < 32) {           // pz block sum of z*cnew
        float v = tq[4*tid] + tq[4*tid+1] + tq[4*tid+2] + tq[4*tid+3];
        #pragma unroll
        for (int o = 16; o; o >>= 1) v += __shfl_down_sync(0xffffffffu, v, o);
        if (tid == 0) g_pz[k] = v;
    }

    // ---- Phase U: u = X @ ynew (rows 2*tid, 2*tid+1) ----
    if (!last) {
        int r = tid * 2;
        const float4* r0p = (const float4*)(At + (size_t)r * NCOL + s);
        const float4* r1p = (const float4*)(At + (size_t)(r + 1) * NCOL + s);
        float u0c = 0.f, u0s = 0.f, u1c = 0.f, u1s = 0.f;
        for (int i4 = 0; i4 < n4; i4++) {
            float4 a = r0p[i4], bq = r1p[i4];
            int ib = i4 * 4;
            float y0 = ycn[ib], y1 = ycn[ib+1], y2 = ycn[ib+2], y3 = ycn[ib+3];
            float t0 = ysn[ib], t1 = ysn[ib+1], t2 = ysn[ib+2], t3 = ysn[ib+3];
            u0c = fmaf(a.x,y0,fmaf(a.y,y1,fmaf(a.z,y2,fmaf(a.w,y3,u0c))));
            u0s = fmaf(a.x,t0,fmaf(a.y,t1,fmaf(a.z,t2,fmaf(a.w,t3,u0s))));
            u1c = fmaf(bq.x,y0,fmaf(bq.y,y1,fmaf(bq.z,y2,fmaf(bq.w,y3,u1c))));
            u1s = fmaf(bq.x,t0,fmaf(bq.y,t1,fmaf(bq.z,t2,fmaf(bq.w,t3,u1s))));
        }
        g_u[0][k][r] = u0c; g_u[0][k][r + 1] = u1c;
        g_u[1][k][r] = u0s; g_u[1][k][r + 1] = u1s;
    }
}

// ---------------- prefixes: U over blocks (per row), Pz scalar ----------------
__global__ __launch_bounds__(128) void prefix_kernel() {
    if (blockIdx.x < 8) {
        int r = blockIdx.x * 128 + threadIdx.x;
        #pragma unroll
        for (int ch = 0; ch < 2; ch++) {
            float run = 0.f;
            #pragma unroll 4
            for (int k = 0; k < NBLK; k++) {
                float t = g_u[ch][k][r];
                g_U[ch][k][r] = run;
                run += t;
            }
        }
    } else if (threadIdx.x < 32) {
        int lane = threadIdx.x;
        float carry = 0.f;
        #pragma unroll
        for (int c2 = 0; c2 < 5; c2++) {
            int idx = c2 * 32 + lane;
            float v = (idx < NBLK) ? g_pz[idx] : 0.f;
            float inc = v;
            #pragma unroll
            for (int o = 1; o < 32; o <<= 1) {
                float u2 = __shfl_up_sync(0xffffffffu, inc, o);
                if (lane >= o) inc += u2;
            }
            if (idx < NBLK) g_Pz[idx] = carry + inc - v;
            carry += __shfl_sync(0xffffffffu, inc, 31);
        }
    }
}

// ---------------- launch ----------------
extern "C" void kernel_launch(void* const* d_in, const int* in_sizes, int n_in,
                              void* d_out, int out_size) {
    const float* At = (const float*)d_in[0];
    const float* b  = (const float*)d_in[1];
    const float* w1 = (const float*)d_in[2];
    const float* W2 = (const float*)d_in[3];
    float* out = (float*)d_out;

    cudaFuncSetAttribute(big_kernel, cudaFuncAttributeMaxDynamicSharedMemorySize, BIGSM);

    init_kernel<<<1, 1024>>>(At, w1);
    t0_kernel<<<16, 256>>>(W2);
    if (out_size >= 2 * NCOL)
        copyb_kernel<<<(NCOL + 255) / 256, 256>>>(b, out);
    gram_kernel<<<dim3(NBLK, 2), 256>>>(At);
    merge_kernel<<<2512, 256>>>();
    zeroYU_kernel<<<160, 1024>>>();

    for (int t = 0; t < NIT; t++) {
        big_kernel<<<NBLK, 512, BIGSM>>>(At, b, out, t == NIT - 1 ? 1 : 0);
        if (t < NIT - 1) prefix_kernel<<<9, 128>>>();
    }
}

// round 5
// speedup vs baseline: 2.0752x; 1.3023x over previous
#include <cuda_runtime.h>

#define D      1024
#define NCOL   20000
#define TWO_M  512
#define DM1    1023
#define BLK    128
#define NBLK   157
#define FETA   1e-5f
#define EPS    (2.0f * FETA)
#define NIT    13
#define NSEG   8
#define SEGW   20
#define XS_STR 132
#define CHROWS 64
#define NCHUNK 16
#define BIGSM  (2 * CHROWS * XS_STR * (int)sizeof(float))   // 67584 B

// ---------------- device globals (no allocation allowed) ----------------
__device__ __align__(16) float g_Spart[2][(size_t)NBLK * BLK * BLK];
__device__ __align__(16) float g_Sall[(size_t)NBLK * BLK * BLK];
__device__ __align__(16) float g_uh[2][2][NBLK][D];   // [slot][chain][blk][row]
__device__ __align__(16) float g_W[2][2][NSEG][D];    // [slot][chain][seg][row]
__device__ float g_pzh[2][NBLK];
__device__ float g_Wz[2][NSEG];
__device__ __align__(16) float g_y[2][NBLK * BLK];
__device__ float g_x0[D];
__device__ float g_T0, g_q0;

// ---------------- init: x0 gather, q0 = w1.x0, zero T0 ----------------
__global__ __launch_bounds__(1024) void init_kernel(const float* __restrict__ At,
                                                    const float* __restrict__ w1) {
    __shared__ float red[32];
    int tid = threadIdx.x;
    float x0 = At[(size_t)tid * NCOL];
    g_x0[tid] = x0;
    float p = w1[tid] * x0;
    #pragma unroll
    for (int o = 16; o; o >>= 1) p += __shfl_down_sync(0xffffffffu, p, o);
    if ((tid & 31) == 0) red[tid >> 5] = p;
    __syncthreads();
    if (tid < 32) {
        float q = red[tid];
        #pragma unroll
        for (int o = 16; o; o >>= 1) q += __shfl_down_sync(0xffffffffu, q, o);
        if (tid == 0) { g_q0 = q; g_T0 = 0.0f; }
    }
}

// ---------------- T0 = ||W2_init @ a_0||^2 ; grid 16 ----------------
__global__ __launch_bounds__(256) void t0_kernel(const float* __restrict__ W2) {
    int wid = threadIdx.x >> 5, lane = threadIdx.x & 31;
    float acc = 0.0f;
    #pragma unroll
    for (int rr = 0; rr < 4; rr++) {
        int m = blockIdx.x * 32 + wid * 4 + rr;
        const float* row = W2 + (size_t)m * DM1;
        float p = 0.0f;
        for (int c = lane; c < DM1; c += 32) p = fmaf(row[c], g_x0[c], p);
        #pragma unroll
        for (int o = 16; o; o >>= 1) p += __shfl_down_sync(0xffffffffu, p, o);
        if (lane == 0) acc = fmaf(p, p, acc);
    }
    if (lane == 0) atomicAdd(&g_T0, acc);
}

// ---------------- copy b into out[N..2N) ----------------
__global__ void copyb_kernel(const float* __restrict__ b, float* __restrict__ out) {
    int i = blockIdx.x * blockDim.x + threadIdx.x;
    if (i < NCOL) out[NCOL + i] = b[i];
}

// ---------------- zero iteration state (both parities) ----------------
__global__ void zero_state_kernel() {
    int idx = blockIdx.x * blockDim.x + threadIdx.x;
    int stride = gridDim.x * blockDim.x;
    float* u = &g_uh[0][0][0][0];
    for (int i = idx; i < 2 * 2 * NBLK * D; i += stride) u[i] = 0.0f;
    float* w = &g_W[0][0][0][0];
    for (int i = idx; i < 2 * 2 * NSEG * D; i += stride) w[i] = 0.0f;
    float* y = &g_y[0][0];
    for (int i = idx; i < 2 * NBLK * BLK; i += stride) y[i] = 0.0f;
    if (idx < 2 * NBLK) (&g_pzh[0][0])[idx] = 0.0f;
    if (idx < 2 * NSEG) (&g_Wz[0][0])[idx] = 0.0f;
}

// ---------------- diag Gram partials; grid (157,2), no atomics ----------------
__global__ __launch_bounds__(256) void gram_kernel(const float* __restrict__ At) {
    __shared__ float sh[32][BLK];
    int k = blockIdx.x, s = k * BLK, kh = blockIdx.y, tid = threadIdx.x;
    int ty = tid >> 4, tx = tid & 15;
    float acc[8][8];
    #pragma unroll
    for (int i = 0; i < 8; i++)
        #pragma unroll
        for (int j = 0; j < 8; j++) acc[i][j] = 0.0f;

    for (int kt = 0; kt < 16; kt++) {
        int r0 = kh * 512 + kt * 32;
        #pragma unroll
        for (int i = 0; i < 4; i++) {
            int f = tid + 256 * i;
            int r = f >> 5;
            int c4 = (f & 31) * 4;
            float4 v = make_float4(0.f, 0.f, 0.f, 0.f);
            if (s + c4 + 3 < NCOL)
                v = *(const float4*)(At + (size_t)(r0 + r) * NCOL + s + c4);
            *(float4*)&sh[r][c4] = v;
        }
        __syncthreads();
        #pragma unroll 4
        for (int r2 = 0; r2 < 32; r2++) {
            float4 a4 = *(const float4*)&sh[r2][8 * ty];
            float4 a5 = *(const float4*)&sh[r2][8 * ty + 4];
            float4 b4 = *(const float4*)&sh[r2][8 * tx];
            float4 b5 = *(const float4*)&sh[r2][8 * tx + 4];
            float av[8] = {a4.x,a4.y,a4.z,a4.w,a5.x,a5.y,a5.z,a5.w};
            float bv[8] = {b4.x,b4.y,b4.z,b4.w,b5.x,b5.y,b5.z,b5.w};
            #pragma unroll
            for (int i = 0; i < 8; i++)
                #pragma unroll
                for (int j = 0; j < 8; j++) acc[i][j] = fmaf(av[i], bv[j], acc[i][j]);
        }
        __syncthreads();
    }
    float* Sk = g_Spart[kh] + (size_t)k * BLK * BLK;
    #pragma unroll
    for (int i = 0; i < 8; i++)
        #pragma unroll
        for (int j = 0; j < 8; j++)
            Sk[(8 * ty + i) * BLK + (8 * tx + j)] = acc[i][j];
}

// ---------------- merge gram halves ----------------
__global__ void merge_kernel() {
    int i = blockIdx.x * blockDim.x + threadIdx.x;
    float4 a = ((const float4*)g_Spart[0])[i];
    float4 b = ((const float4*)g_Spart[1])[i];
    ((float4*)g_Sall)[i] = make_float4(a.x + b.x, a.y + b.y, a.z + b.z, a.w + b.w);
}

// ---------------- one fused Jacobi sweep: 157 CTAs, all blocks parallel ----------------
// parity p: reads W[p], u[p^1], pz[p], Wz[p]; writes u[p], pz[p], W[p^1], Wz[p^1]
__global__ __launch_bounds__(512) void big_kernel(const float* __restrict__ At,
                                                  const float* __restrict__ b,
                                                  float* __restrict__ out,
                                                  int p, int last) {
    extern __shared__ float dsm[];                 // 2 chunk buffers / later S
    __shared__ float Ucm[D], Usm[D];
    __shared__ float pAc[16][BLK], pAs[16][BLK];
    __shared__ float plc[4][BLK], pls[4][BLK];
    __shared__ float yco[BLK], yso[BLK], ycn[BLK], ysn[BLK];
    __shared__ float zz[BLK], bb[BLK], tq[BLK], pref[BLK];
    __shared__ float sPz;

    const int tid = threadIdx.x;
    const int k = blockIdx.x;
    const int s = k * BLK;
    const int n = (NCOL - s < BLK) ? (NCOL - s) : BLK;
    const int n4 = n >> 2;
    const int seg = k / SEGW;
    const int segbase = seg * SEGW;
    const int pr = p ^ 1;

    // ---- build exclusive-prefix coupling vectors from segment sums + same-seg u ----
    #pragma unroll
    for (int half = 0; half < 2; half++) {
        int rr = tid + 512 * half;
        float uc = 0.f, us = 0.f;
        for (int s2 = 0; s2 < seg; s2++) {
            uc += g_W[p][0][s2][rr];
            us += g_W[p][1][s2][rr];
        }
        for (int k2 = segbase; k2 < k; k2++) {
            uc += g_uh[pr][0][k2][rr];
            us += g_uh[pr][1][k2][rr];
        }
        Ucm[rr] = uc; Usm[rr] = us;
    }
    if (tid == 0) {
        float a = 0.f;
        for (int s2 = 0; s2 < seg; s2++) a += g_Wz[p][s2];
        for (int k2 = segbase; k2 < k; k2++) a += g_pzh[pr][k2];
        sPz = a;
    }
    if (tid < BLK) {
        yco[tid] = g_y[0][k * BLK + tid];
        yso[tid] = g_y[1][k * BLK + tid];
        zz[tid] = (tid < n) ? At[(size_t)DM1 * NCOL + s + tid] : 0.f;
        bb[tid] = (tid < n) ? b[s + tid] : 0.f;
    }
    __syncthreads();

    // ---- Phase A: coupling dots (x_i . U) over 16 chunks of 64 rows, double-buffered ----
    const int wrp = tid >> 5;          // 0..15
    const int cg = (tid & 31) * 4;
    float4 vcA = make_float4(0.f,0.f,0.f,0.f), vsA = make_float4(0.f,0.f,0.f,0.f);
    float* buf0 = dsm;
    float* buf1 = dsm + CHROWS * XS_STR;

    float4 ld[4];
    #pragma unroll
    for (int ii = 0; ii < 4; ii++) {
        int f = tid + 512 * ii; int r = f >> 5, c4 = (f & 31) * 4;
        ld[ii] = (c4 < n) ? *(const float4*)(At + (size_t)r * NCOL + s + c4)
                          : make_float4(0.f,0.f,0.f,0.f);
    }
    #pragma unroll
    for (int ii = 0; ii < 4; ii++) {
        int f = tid + 512 * ii; int r = f >> 5, c4 = (f & 31) * 4;
        *(float4*)&buf0[r * XS_STR + c4] = ld[ii];
    }
    __syncthreads();

    for (int ch = 0; ch < NCHUNK; ch++) {
        float* cur = (ch & 1) ? buf1 : buf0;
        float* nxt = (ch & 1) ? buf0 : buf1;
        if (ch + 1 < NCHUNK) {
            int rb = (ch + 1) * CHROWS;
            #pragma unroll
            for (int ii = 0; ii < 4; ii++) {
                int f = tid + 512 * ii; int r = f >> 5, c4 = (f & 31) * 4;
                ld[ii] = (c4 < n) ? *(const float4*)(At + (size_t)(rb + r) * NCOL + s + c4)
                                  : make_float4(0.f,0.f,0.f,0.f);
            }
        }
        #pragma unroll
        for (int r2 = 0; r2 < 4; r2++) {
            int rr = wrp * 4 + r2;
            float uc = Ucm[ch * CHROWS + rr], us = Usm[ch * CHROWS + rr];
            float4 xv = *(const float4*)&cur[rr * XS_STR + cg];
            vcA.x = fmaf(uc, xv.x, vcA.x); vcA.y = fmaf(uc, xv.y, vcA.y);
            vcA.z = fmaf(uc, xv.z, vcA.z); vcA.w = fmaf(uc, xv.w, vcA.w);
            vsA.x = fmaf(us, xv.x, vsA.x); vsA.y = fmaf(us, xv.y, vsA.y);
            vsA.z = fmaf(us, xv.z, vsA.z); vsA.w = fmaf(us, xv.w, vsA.w);
        }
        if (ch + 1 < NCHUNK) {
            __syncthreads();
            #pragma unroll
            for (int ii = 0; ii < 4; ii++) {
                int f = tid + 512 * ii; int r = f >> 5, c4 = (f & 31) * 4;
                *(float4*)&nxt[r * XS_STR + c4] = ld[ii];
            }
            __syncthreads();
        }
    }
    *(float4*)&pAc[wrp][cg] = vcA;
    *(float4*)&pAs[wrp][cg] = vsA;
    __syncthreads();

    // ---- stage local Gram S into dsm ----
    {
        const float4* Sg = (const float4*)(g_Sall + (size_t)k * BLK * BLK);
        float4* Ss = (float4*)dsm;
        #pragma unroll
        for (int ii = 0; ii < 8; ii++) Ss[tid + 512 * ii] = Sg[tid + 512 * ii];
    }
    if (tid < BLK) tq[tid] = zz[tid] * yco[tid];
    __syncthreads();

    // ---- local strict-lower matvecs (both chains) ----
    {
        const int qq = tid >> 7, i = tid & 127, jb = qq * 32;
        float lc = 0.f, ls = 0.f;
        #pragma unroll 8
        for (int j2 = 0; j2 < 32; j2++) {
            int j = jb + j2;
            if (j < i) {
                float sv = dsm[j * BLK + i];
                lc = fmaf(sv, yco[j], lc);
                ls = fmaf(sv, yso[j], ls);
            }
        }
        plc[qq][i] = lc; pls[qq][i] = ls;
    }
    if (tid < 32) {          // exclusive prefix of z*yc_old
        float v0 = tq[4*tid], v1 = tq[4*tid+1], v2 = tq[4*tid+2], v3 = tq[4*tid+3];
        float i0 = v0, i1 = i0 + v1, i2 = i1 + v2, i3 = i2 + v3;
        float run = i3;
        #pragma unroll
        for (int o = 1; o < 32; o <<= 1) {
            float u2 = __shfl_up_sync(0xffffffffu, run, o);
            if ((int)tid >= o) run += u2;
        }
        float ex = run - i3;
        pref[4*tid] = ex; pref[4*tid+1] = ex + i0;
        pref[4*tid+2] = ex + i1; pref[4*tid+3] = ex + i2;
    }
    __syncthreads();

    // ---- combine + Jacobi update ----
    if (tid < BLK) {
        const int i = tid;
        float cc = 0.f, cs = 0.f;
        #pragma unroll
        for (int pp = 0; pp < 16; pp++) { cc += pAc[pp][i]; cs += pAs[pp][i]; }
        float lc = plc[0][i] + plc[1][i] + plc[2][i] + plc[3][i];
        float ls = pls[0][i] + pls[1][i] + pls[2][i] + pls[3][i];
        float zp = sPz + pref[i];
        float rc = (s + i == 0) ? 1.0f : 0.0f;
        float cnew = rc - EPS * (cc + lc - zz[i] * zp);
        float rs = fmaf(2.0f * g_T0, cnew * cnew, -2.0f * bb[i]);
        if (s + i == 0) rs += 2.0f * g_q0;
        float snew = rs - EPS * (cs + ls);
        ycn[i] = cnew; ysn[i] = snew;
        g_y[0][k * BLK + i] = cnew;
        g_y[1][k * BLK + i] = snew;
        if (last && i < n) out[s + i] = fmaf(0.5f, snew, bb[i]);
        tq[i] = zz[i] * cnew;
    }
    __syncthreads();

    if (last) return;

    if (tid < 32) {           // pz block sum of z*cnew, publish + segment delta
        float v = tq[4*tid] + tq[4*tid+1] + tq[4*tid+2] + tq[4*tid+3];
        #pragma unroll
        for (int o = 16; o; o >>= 1) v += __shfl_down_sync(0xffffffffu, v, o);
        if (tid == 0) {
            float old = g_pzh[p][k];
            g_pzh[p][k] = v;
            atomicAdd(&g_Wz[pr][seg], v - old);
        }
    }

    // ---- Phase U: u = X @ ynew (rows 2*tid, 2*tid+1) + segment-sum deltas ----
    {
        int r = tid * 2;
        const float4* r0p = (const float4*)(At + (size_t)r * NCOL + s);
        const float4* r1p = (const float4*)(At + (size_t)(r + 1) * NCOL + s);
        float u0c = 0.f, u0s = 0.f, u1c = 0.f, u1s = 0.f;
        for (int i4 = 0; i4 < n4; i4++) {
            float4 a = r0p[i4], bq = r1p[i4];
            int ib = i4 * 4;
            float y0 = ycn[ib], y1 = ycn[ib+1], y2 = ycn[ib+2], y3 = ycn[ib+3];
            float t0 = ysn[ib], t1 = ysn[ib+1], t2 = ysn[ib+2], t3 = ysn[ib+3];
            u0c = fmaf(a.x,y0,fmaf(a.y,y1,fmaf(a.z,y2,fmaf(a.w,y3,u0c))));
            u0s = fmaf(a.x,t0,fmaf(a.y,t1,fmaf(a.z,t2,fmaf(a.w,t3,u0s))));
            u1c = fmaf(bq.x,y0,fmaf(bq.y,y1,fmaf(bq.z,y2,fmaf(bq.w,y3,u1c))));
            u1s = fmaf(bq.x,t0,fmaf(bq.y,t1,fmaf(bq.z,t2,fmaf(bq.w,t3,u1s))));
        }
        float o0c = g_uh[p][0][k][r], o1c = g_uh[p][0][k][r+1];
        float o0s = g_uh[p][1][k][r], o1s = g_uh[p][1][k][r+1];
        g_uh[p][0][k][r] = u0c; g_uh[p][0][k][r+1] = u1c;
        g_uh[p][1][k][r] = u0s; g_uh[p][1][k][r+1] = u1s;
        atomicAdd(&g_W[pr][0][seg][r],     u0c - o0c);
        atomicAdd(&g_W[pr][0][seg][r + 1], u1c - o1c);
        atomicAdd(&g_W[pr][1][seg][r],     u0s - o0s);
        atomicAdd(&g_W[pr][1][seg][r + 1], u1s - o1s);
    }
}

// ---------------- launch ----------------
extern "C" void kernel_launch(void* const* d_in, const int* in_sizes, int n_in,
                              void* d_out, int out_size) {
    const float* At = (const float*)d_in[0];
    const float* b  = (const float*)d_in[1];
    const float* w1 = (const float*)d_in[2];
    const float* W2 = (const float*)d_in[3];
    float* out = (float*)d_out;

    cudaFuncSetAttribute(big_kernel, cudaFuncAttributeMaxDynamicSharedMemorySize, BIGSM);

    init_kernel<<<1, 1024>>>(At, w1);
    t0_kernel<<<16, 256>>>(W2);
    if (out_size >= 2 * NCOL)
        copyb_kernel<<<(NCOL + 255) / 256, 256>>>(b, out);
    gram_kernel<<<dim3(NBLK, 2), 256>>>(At);
    merge_kernel<<<2512, 256>>>();
    zero_state_kernel<<<160, 1024>>>();

    for (int t = 0; t < NIT; t++)
        big_kernel<<<NBLK, 512, BIGSM>>>(At, b, out, t & 1, t == NIT - 1 ? 1 : 0);
}

// round 6
// speedup vs baseline: 2.6447x; 1.2744x over previous
#include <cuda_runtime.h>

#define D      1024
#define NCOL   20000
#define TWO_M  512
#define DM1    1023
#define BLK    128
#define NBLK   157
#define FETA   1e-5f
#define EPS    (2.0f * FETA)
#define NIT    10
#define NSEG   8
#define SEGW   20
#define BIGSM  (BLK * BLK * (int)sizeof(float))   // 65536 B (S tile)

// ---------------- device globals (no allocation allowed) ----------------
__device__ __align__(16) float g_Spart[2][(size_t)NBLK * BLK * BLK];
__device__ __align__(16) float g_Sall[(size_t)NBLK * BLK * BLK];
__device__ __align__(16) float g_uh[2][2][NBLK][D];   // [slot][chain][blk][row]
__device__ __align__(16) float g_W[2][2][NSEG][D];    // [slot][chain][seg][row]
__device__ float g_pzh[2][NBLK];
__device__ float g_Wz[2][NSEG];
__device__ __align__(16) float g_y[2][NBLK * BLK];
__device__ float g_x0[D];
__device__ float g_T0, g_q0;

// ---------------- init: x0 gather, q0 = w1.x0, zero T0 ----------------
__global__ __launch_bounds__(1024) void init_kernel(const float* __restrict__ At,
                                                    const float* __restrict__ w1) {
    __shared__ float red[32];
    int tid = threadIdx.x;
    float x0 = At[(size_t)tid * NCOL];
    g_x0[tid] = x0;
    float p = w1[tid] * x0;
    #pragma unroll
    for (int o = 16; o; o >>= 1) p += __shfl_down_sync(0xffffffffu, p, o);
    if ((tid & 31) == 0) red[tid >> 5] = p;
    __syncthreads();
    if (tid < 32) {
        float q = red[tid];
        #pragma unroll
        for (int o = 16; o; o >>= 1) q += __shfl_down_sync(0xffffffffu, q, o);
        if (tid == 0) { g_q0 = q; g_T0 = 0.0f; }
    }
}

// ---------------- T0 = ||W2_init @ a_0||^2 ; grid 16 ----------------
__global__ __launch_bounds__(256) void t0_kernel(const float* __restrict__ W2) {
    int wid = threadIdx.x >> 5, lane = threadIdx.x & 31;
    float acc = 0.0f;
    #pragma unroll
    for (int rr = 0; rr < 4; rr++) {
        int m = blockIdx.x * 32 + wid * 4 + rr;
        const float* row = W2 + (size_t)m * DM1;
        float p = 0.0f;
        for (int c = lane; c < DM1; c += 32) p = fmaf(row[c], g_x0[c], p);
        #pragma unroll
        for (int o = 16; o; o >>= 1) p += __shfl_down_sync(0xffffffffu, p, o);
        if (lane == 0) acc = fmaf(p, p, acc);
    }
    if (lane == 0) atomicAdd(&g_T0, acc);
}

// ---------------- copy b into out[N..2N) ----------------
__global__ void copyb_kernel(const float* __restrict__ b, float* __restrict__ out) {
    int i = blockIdx.x * blockDim.x + threadIdx.x;
    if (i < NCOL) out[NCOL + i] = b[i];
}

// ---------------- zero iteration state (both parities) ----------------
__global__ void zero_state_kernel() {
    int idx = blockIdx.x * blockDim.x + threadIdx.x;
    int stride = gridDim.x * blockDim.x;
    float* u = &g_uh[0][0][0][0];
    for (int i = idx; i < 2 * 2 * NBLK * D; i += stride) u[i] = 0.0f;
    float* w = &g_W[0][0][0][0];
    for (int i = idx; i < 2 * 2 * NSEG * D; i += stride) w[i] = 0.0f;
    float* y = &g_y[0][0];
    for (int i = idx; i < 2 * NBLK * BLK; i += stride) y[i] = 0.0f;
    if (idx < 2 * NBLK) (&g_pzh[0][0])[idx] = 0.0f;
    if (idx < 2 * NSEG) (&g_Wz[0][0])[idx] = 0.0f;
}

// ---------------- diag Gram partials; grid (157,2), no atomics ----------------
__global__ __launch_bounds__(256) void gram_kernel(const float* __restrict__ At) {
    __shared__ float sh[32][BLK];
    int k = blockIdx.x, s = k * BLK, kh = blockIdx.y, tid = threadIdx.x;
    int ty = tid >> 4, tx = tid & 15;
    float acc[8][8];
    #pragma unroll
    for (int i = 0; i < 8; i++)
        #pragma unroll
        for (int j = 0; j < 8; j++) acc[i][j] = 0.0f;

    for (int kt = 0; kt < 16; kt++) {
        int r0 = kh * 512 + kt * 32;
        #pragma unroll
        for (int i = 0; i < 4; i++) {
            int f = tid + 256 * i;
            int r = f >> 5;
            int c4 = (f & 31) * 4;
            float4 v = make_float4(0.f, 0.f, 0.f, 0.f);
            if (s + c4 + 3 < NCOL)
                v = *(const float4*)(At + (size_t)(r0 + r) * NCOL + s + c4);
            *(float4*)&sh[r][c4] = v;
        }
        __syncthreads();
        #pragma unroll 4
        for (int r2 = 0; r2 < 32; r2++) {
            float4 a4 = *(const float4*)&sh[r2][8 * ty];
            float4 a5 = *(const float4*)&sh[r2][8 * ty + 4];
            float4 b4 = *(const float4*)&sh[r2][8 * tx];
            float4 b5 = *(const float4*)&sh[r2][8 * tx + 4];
            float av[8] = {a4.x,a4.y,a4.z,a4.w,a5.x,a5.y,a5.z,a5.w};
            float bv[8] = {b4.x,b4.y,b4.z,b4.w,b5.x,b5.y,b5.z,b5.w};
            #pragma unroll
            for (int i = 0; i < 8; i++)
                #pragma unroll
                for (int j = 0; j < 8; j++) acc[i][j] = fmaf(av[i], bv[j], acc[i][j]);
        }
        __syncthreads();
    }
    float* Sk = g_Spart[kh] + (size_t)k * BLK * BLK;
    #pragma unroll
    for (int i = 0; i < 8; i++)
        #pragma unroll
        for (int j = 0; j < 8; j++)
            Sk[(8 * ty + i) * BLK + (8 * tx + j)] = acc[i][j];
}

// ---------------- merge gram halves ----------------
__global__ void merge_kernel() {
    int i = blockIdx.x * blockDim.x + threadIdx.x;
    float4 a = ((const float4*)g_Spart[0])[i];
    float4 b = ((const float4*)g_Spart[1])[i];
    ((float4*)g_Sall)[i] = make_float4(a.x + b.x, a.y + b.y, a.z + b.z, a.w + b.w);
}

// ---------------- one fused Jacobi sweep: 157 CTAs, all blocks parallel ----------------
// parity p: reads W[p], u[p^1], pz[p], Wz[p]; writes u[p], pz[p], W[p^1], Wz[p^1]
__global__ __launch_bounds__(512) void big_kernel(const float* __restrict__ At,
                                                  const float* __restrict__ b,
                                                  float* __restrict__ out,
                                                  int p, int last) {
    extern __shared__ float dsm[];                 // S tile (128x128)
    __shared__ float Ucm[D], Usm[D];
    __shared__ float pAc[16][BLK], pAs[16][BLK];
    __shared__ float plc[4][BLK], pls[4][BLK];
    __shared__ float yco[BLK], yso[BLK], ycn[BLK], ysn[BLK];
    __shared__ float zz[BLK], bb[BLK], tq[BLK], pref[BLK];
    __shared__ float sPz;

    const int tid = threadIdx.x;
    const int w = tid >> 5, lane = tid & 31;
    const int k = blockIdx.x;
    const int s = k * BLK;
    const int n = (NCOL - s < BLK) ? (NCOL - s) : BLK;
    const int seg = k / SEGW;
    const int segbase = seg * SEGW;
    const int pr = p ^ 1;

    // ---- build exclusive-prefix coupling vectors from segment sums + same-seg u ----
    #pragma unroll
    for (int half = 0; half < 2; half++) {
        int rr = tid + 512 * half;
        float uc = 0.f, us = 0.f;
        #pragma unroll 2
        for (int s2 = 0; s2 < seg; s2++) {
            uc += g_W[p][0][s2][rr];
            us += g_W[p][1][s2][rr];
        }
        #pragma unroll 4
        for (int k2 = segbase; k2 < k; k2++) {
            uc += g_uh[pr][0][k2][rr];
            us += g_uh[pr][1][k2][rr];
        }
        Ucm[rr] = uc; Usm[rr] = us;
    }
    if (tid == 0) {
        float a = 0.f;
        for (int s2 = 0; s2 < seg; s2++) a += g_Wz[p][s2];
        for (int k2 = segbase; k2 < k; k2++) a += g_pzh[pr][k2];
        sPz = a;
    }
    if (tid < BLK) {
        yco[tid] = g_y[0][k * BLK + tid];
        yso[tid] = g_y[1][k * BLK + tid];
        zz[tid] = (tid < n) ? At[(size_t)DM1 * NCOL + s + tid] : 0.f;
        bb[tid] = (tid < n) ? b[s + tid] : 0.f;
    }
    __syncthreads();

    // ---- Phase A: coupling dots (x_i . U), direct coalesced loads, no staging ----
    {
        const int colb = lane * 4;
        float4 vcA = make_float4(0.f,0.f,0.f,0.f), vsA = make_float4(0.f,0.f,0.f,0.f);
        if (colb < n) {
            const float* Xw = At + (size_t)(w * 64) * NCOL + s + colb;
            #pragma unroll 8
            for (int r = 0; r < 64; r++) {
                float uc = Ucm[w * 64 + r], us = Usm[w * 64 + r];
                float4 xv = *(const float4*)(Xw + (size_t)r * NCOL);
                vcA.x = fmaf(uc, xv.x, vcA.x); vcA.y = fmaf(uc, xv.y, vcA.y);
                vcA.z = fmaf(uc, xv.z, vcA.z); vcA.w = fmaf(uc, xv.w, vcA.w);
                vsA.x = fmaf(us, xv.x, vsA.x); vsA.y = fmaf(us, xv.y, vsA.y);
                vsA.z = fmaf(us, xv.z, vsA.z); vsA.w = fmaf(us, xv.w, vsA.w);
            }
        }
        *(float4*)&pAc[w][colb] = vcA;
        *(float4*)&pAs[w][colb] = vsA;
    }

    // ---- stage local Gram S into dsm (independent of phase A) ----
    {
        const float4* Sg = (const float4*)(g_Sall + (size_t)k * BLK * BLK);
        float4* Ss = (float4*)dsm;
        #pragma unroll
        for (int ii = 0; ii < 8; ii++) Ss[tid + 512 * ii] = Sg[tid + 512 * ii];
    }
    if (tid < BLK) tq[tid] = zz[tid] * yco[tid];
    __syncthreads();

    // ---- local strict-lower matvecs (both chains) ----
    {
        const int qq = tid >> 7, i = tid & 127, jb = qq * 32;
        float lc = 0.f, ls = 0.f;
        #pragma unroll 8
        for (int j2 = 0; j2 < 32; j2++) {
            int j = jb + j2;
            if (j < i) {
                float sv = dsm[j * BLK + i];
                lc = fmaf(sv, yco[j], lc);
                ls = fmaf(sv, yso[j], ls);
            }
        }
        plc[qq][i] = lc; pls[qq][i] = ls;
    }
    if (tid < 32) {          // exclusive prefix of z*yc_old
        float v0 = tq[4*tid], v1 = tq[4*tid+1], v2 = tq[4*tid+2], v3 = tq[4*tid+3];
        float i0 = v0, i1 = i0 + v1, i2 = i1 + v2, i3 = i2 + v3;
        float run = i3;
        #pragma unroll
        for (int o = 1; o < 32; o <<= 1) {
            float u2 = __shfl_up_sync(0xffffffffu, run, o);
            if ((int)tid >= o) run += u2;
        }
        float ex = run - i3;
        pref[4*tid] = ex; pref[4*tid+1] = ex + i0;
        pref[4*tid+2] = ex + i1; pref[4*tid+3] = ex + i2;
    }
    __syncthreads();

    // ---- combine + Jacobi update ----
    if (tid < BLK) {
        const int i = tid;
        float cc = 0.f, cs = 0.f;
        #pragma unroll
        for (int pp = 0; pp < 16; pp++) { cc += pAc[pp][i]; cs += pAs[pp][i]; }
        float lc = plc[0][i] + plc[1][i] + plc[2][i] + plc[3][i];
        float ls = pls[0][i] + pls[1][i] + pls[2][i] + pls[3][i];
        float zp = sPz + pref[i];
        float rc = (s + i == 0) ? 1.0f : 0.0f;
        float cnew = rc - EPS * (cc + lc - zz[i] * zp);
        float rs = fmaf(2.0f * g_T0, cnew * cnew, -2.0f * bb[i]);
        if (s + i == 0) rs += 2.0f * g_q0;
        float snew = rs - EPS * (cs + ls);
        ycn[i] = cnew; ysn[i] = snew;
        g_y[0][k * BLK + i] = cnew;
        g_y[1][k * BLK + i] = snew;
        if (last && i < n) out[s + i] = fmaf(0.5f, snew, bb[i]);
        tq[i] = zz[i] * cnew;
    }
    __syncthreads();

    if (last) return;

    if (tid < 32) {           // pz block sum of z*cnew, publish + segment delta
        float v = tq[4*tid] + tq[4*tid+1] + tq[4*tid+2] + tq[4*tid+3];
        #pragma unroll
        for (int o = 16; o; o >>= 1) v += __shfl_down_sync(0xffffffffu, v, o);
        if (tid == 0) {
            float old = g_pzh[p][k];
            g_pzh[p][k] = v;
            atomicAdd(&g_Wz[pr][seg], v - old);
        }
    }

    // ---- Phase U: u = X @ ynew; 8-lane groups per row, coalesced 128B chunks ----
    {
        const int g8 = lane >> 3, gl = lane & 7;     // 4 groups of 8 lanes
        for (int pass = 0; pass < 16; pass++) {
            int r = w * 64 + pass * 4 + g8;
            const float* rp = At + (size_t)r * NCOL + s;
            float uc = 0.f, us = 0.f;
            #pragma unroll
            for (int it = 0; it < 4; it++) {
                int col = it * 32 + gl * 4;
                if (col < n) {
                    float4 xv = *(const float4*)(rp + col);
                    uc = fmaf(xv.x, ycn[col],   fmaf(xv.y, ycn[col+1],
                         fmaf(xv.z, ycn[col+2], fmaf(xv.w, ycn[col+3], uc))));
                    us = fmaf(xv.x, ysn[col],   fmaf(xv.y, ysn[col+1],
                         fmaf(xv.z, ysn[col+2], fmaf(xv.w, ysn[col+3], us))));
                }
            }
            #pragma unroll
            for (int o = 4; o; o >>= 1) {
                uc += __shfl_down_sync(0xffffffffu, uc, o, 8);
                us += __shfl_down_sync(0xffffffffu, us, o, 8);
            }
            if (gl == 0) {
                float oc = g_uh[p][0][k][r], os = g_uh[p][1][k][r];
                g_uh[p][0][k][r] = uc;
                g_uh[p][1][k][r] = us;
                atomicAdd(&g_W[pr][0][seg][r], uc - oc);
                atomicAdd(&g_W[pr][1][seg][r], us - os);
            }
        }
    }
}

// ---------------- launch ----------------
extern "C" void kernel_launch(void* const* d_in, const int* in_sizes, int n_in,
                              void* d_out, int out_size) {
    const float* At = (const float*)d_in[0];
    const float* b  = (const float*)d_in[1];
    const float* w1 = (const float*)d_in[2];
    const float* W2 = (const float*)d_in[3];
    float* out = (float*)d_out;

    cudaFuncSetAttribute(big_kernel, cudaFuncAttributeMaxDynamicSharedMemorySize, BIGSM);

    init_kernel<<<1, 1024>>>(At, w1);
    t0_kernel<<<16, 256>>>(W2);
    if (out_size >= 2 * NCOL)
        copyb_kernel<<<(NCOL + 255) / 256, 256>>>(b, out);
    gram_kernel<<<dim3(NBLK, 2), 256>>>(At);
    merge_kernel<<<2512, 256>>>();
    zero_state_kernel<<<160, 1024>>>();

    for (int t = 0; t < NIT; t++)
        big_kernel<<<NBLK, 512, BIGSM>>>(At, b, out, t & 1, t == NIT - 1 ? 1 : 0);
}

// round 7
// speedup vs baseline: 3.8120x; 1.4414x over previous
#include <cuda_runtime.h>

#define D      1024
#define NCOL   20000
#define TWO_M  512
#define DM1    1023
#define BLK    128
#define NBLK   157
#define FETA   1e-5f
#define EPS    (2.0f * FETA)
#define NIT    7
#define NSEG   8
#define SEGW   20
#define BIGSM  (BLK * BLK * (int)sizeof(float))   // 65536 B (S tile)

// ---------------- device globals (no allocation allowed) ----------------
__device__ __align__(16) float g_Sall[(size_t)NBLK * BLK * BLK];   // 10.3 MB
__device__ __align__(16) float g_uh[2][2][NBLK][D];   // [slot][chain][blk][row]
__device__ __align__(16) float g_W[2][2][NSEG][D];    // [slot][chain][seg][row]
__device__ float g_pzh[2][NBLK];
__device__ float g_Wz[2][NSEG];
__device__ __align__(16) float g_y[2][NBLK * BLK];
__device__ float g_x0[D];
__device__ float g_T0, g_q0;

// ---------------- init: x0 gather, q0 = w1.x0, zero T0 ----------------
__global__ __launch_bounds__(1024) void init_kernel(const float* __restrict__ At,
                                                    const float* __restrict__ w1) {
    __shared__ float red[32];
    int tid = threadIdx.x;
    float x0 = At[(size_t)tid * NCOL];
    g_x0[tid] = x0;
    float p = w1[tid] * x0;
    #pragma unroll
    for (int o = 16; o; o >>= 1) p += __shfl_down_sync(0xffffffffu, p, o);
    if ((tid & 31) == 0) red[tid >> 5] = p;
    __syncthreads();
    if (tid < 32) {
        float q = red[tid];
        #pragma unroll
        for (int o = 16; o; o >>= 1) q += __shfl_down_sync(0xffffffffu, q, o);
        if (tid == 0) { g_q0 = q; g_T0 = 0.0f; }
    }
}

// ---------------- T0 = ||W2_init @ a_0||^2 ; grid 16 ----------------
__global__ __launch_bounds__(256) void t0_kernel(const float* __restrict__ W2) {
    int wid = threadIdx.x >> 5, lane = threadIdx.x & 31;
    float acc = 0.0f;
    #pragma unroll
    for (int rr = 0; rr < 4; rr++) {
        int m = blockIdx.x * 32 + wid * 4 + rr;
        const float* row = W2 + (size_t)m * DM1;
        float p = 0.0f;
        for (int c = lane; c < DM1; c += 32) p = fmaf(row[c], g_x0[c], p);
        #pragma unroll
        for (int o = 16; o; o >>= 1) p += __shfl_down_sync(0xffffffffu, p, o);
        if (lane == 0) acc = fmaf(p, p, acc);
    }
    if (lane == 0) atomicAdd(&g_T0, acc);
}

// ---------------- copy b into out[N..2N) ----------------
__global__ void copyb_kernel(const float* __restrict__ b, float* __restrict__ out) {
    int i = blockIdx.x * blockDim.x + threadIdx.x;
    if (i < NCOL) out[NCOL + i] = b[i];
}

// ---------------- zero iteration state (both parities) ----------------
__global__ void zero_state_kernel() {
    int idx = blockIdx.x * blockDim.x + threadIdx.x;
    int stride = gridDim.x * blockDim.x;
    float* u = &g_uh[0][0][0][0];
    for (int i = idx; i < 2 * 2 * NBLK * D; i += stride) u[i] = 0.0f;
    float* w = &g_W[0][0][0][0];
    for (int i = idx; i < 2 * 2 * NSEG * D; i += stride) w[i] = 0.0f;
    float* y = &g_y[0][0];
    for (int i = idx; i < 2 * NBLK * BLK; i += stride) y[i] = 0.0f;
    if (idx < 2 * NBLK) (&g_pzh[0][0])[idx] = 0.0f;
    if (idx < 2 * NSEG) (&g_Wz[0][0])[idx] = 0.0f;
}

// ---------------- diag Gram blocks; grid 157, 512 thr, full K, one wave ----------------
__global__ __launch_bounds__(512, 2) void gram_kernel(const float* __restrict__ At) {
    __shared__ float sh[32][BLK];
    const int k = blockIdx.x, s = k * BLK, tid = threadIdx.x;
    const int ty = tid >> 4;          // 0..31 -> rows 4*ty..4*ty+3
    const int tx = tid & 15;          // 0..15 -> cols 8*tx..8*tx+7
    float acc[4][8];
    #pragma unroll
    for (int i = 0; i < 4; i++)
        #pragma unroll
        for (int j = 0; j < 8; j++) acc[i][j] = 0.0f;

    for (int kt = 0; kt < 32; kt++) {
        int r0 = kt * 32;
        #pragma unroll
        for (int i = 0; i < 2; i++) {
            int f = tid + 512 * i;            // 1024 float4
            int r = f >> 5;
            int c4 = (f & 31) * 4;
            float4 v = make_float4(0.f, 0.f, 0.f, 0.f);
            if (s + c4 + 3 < NCOL)
                v = *(const float4*)(At + (size_t)(r0 + r) * NCOL + s + c4);
            *(float4*)&sh[r][c4] = v;
        }
        __syncthreads();
        #pragma unroll 8
        for (int r2 = 0; r2 < 32; r2++) {
            float4 a4 = *(const float4*)&sh[r2][4 * ty];
            float4 b4 = *(const float4*)&sh[r2][8 * tx];
            float4 b5 = *(const float4*)&sh[r2][8 * tx + 4];
            float av[4] = {a4.x, a4.y, a4.z, a4.w};
            float bv[8] = {b4.x, b4.y, b4.z, b4.w, b5.x, b5.y, b5.z, b5.w};
            #pragma unroll
            for (int i = 0; i < 4; i++)
                #pragma unroll
                for (int j = 0; j < 8; j++) acc[i][j] = fmaf(av[i], bv[j], acc[i][j]);
        }
        __syncthreads();
    }
    float* Sk = g_Sall + (size_t)k * BLK * BLK;
    #pragma unroll
    for (int i = 0; i < 4; i++) {
        int row = 4 * ty + i;
        *(float4*)&Sk[row * BLK + 8 * tx]     = make_float4(acc[i][0], acc[i][1], acc[i][2], acc[i][3]);
        *(float4*)&Sk[row * BLK + 8 * tx + 4] = make_float4(acc[i][4], acc[i][5], acc[i][6], acc[i][7]);
    }
}

// ---------------- one fused Jacobi sweep: 157 CTAs, all blocks parallel ----------------
// parity p: reads W[p], u[p^1], pz[p], Wz[p]; writes u[p], pz[p], W[p^1], Wz[p^1]
__global__ __launch_bounds__(512) void big_kernel(const float* __restrict__ At,
                                                  const float* __restrict__ b,
                                                  float* __restrict__ out,
                                                  int p, int last) {
    extern __shared__ float dsm[];                 // S tile (128x128)
    __shared__ float Ucm[D], Usm[D];
    __shared__ float pAc[16][BLK], pAs[16][BLK];
    __shared__ float plc[4][BLK], pls[4][BLK];
    __shared__ float yco[BLK], yso[BLK], ycn[BLK], ysn[BLK];
    __shared__ float zz[BLK], bb[BLK], tq[BLK], pref[BLK];
    __shared__ float sPz;

    const int tid = threadIdx.x;
    const int w = tid >> 5, lane = tid & 31;
    const int k = blockIdx.x;
    const int s = k * BLK;
    const int n = (NCOL - s < BLK) ? (NCOL - s) : BLK;
    const int seg = k / SEGW;
    const int segbase = seg * SEGW;
    const int pr = p ^ 1;

    // ---- build exclusive-prefix coupling vectors (float4 path) ----
    {
        const int chain = tid >> 8;       // 0 = c, 1 = sg
        const int slot = tid & 255;       // float4 slot within 1024-float vector
        const float4* Wp = (const float4*)&g_W[p][chain][0][0];
        const float4* up = (const float4*)&g_uh[pr][chain][0][0];
        float4 acc = make_float4(0.f, 0.f, 0.f, 0.f);
        #pragma unroll 2
        for (int s2 = 0; s2 < seg; s2++) {
            float4 v = Wp[s2 * 256 + slot];
            acc.x += v.x; acc.y += v.y; acc.z += v.z; acc.w += v.w;
        }
        #pragma unroll 4
        for (int k2 = segbase; k2 < k; k2++) {
            float4 v = up[k2 * 256 + slot];
            acc.x += v.x; acc.y += v.y; acc.z += v.z; acc.w += v.w;
        }
        float4* dst = (float4*)(chain ? Usm : Ucm);
        dst[slot] = acc;
    }
    if (tid == 0) {
        float a = 0.f;
        for (int s2 = 0; s2 < seg; s2++) a += g_Wz[p][s2];
        for (int k2 = segbase; k2 < k; k2++) a += g_pzh[pr][k2];
        sPz = a;
    }
    if (tid < BLK) {
        yco[tid] = g_y[0][k * BLK + tid];
        yso[tid] = g_y[1][k * BLK + tid];
        zz[tid] = (tid < n) ? At[(size_t)DM1 * NCOL + s + tid] : 0.f;
        bb[tid] = (tid < n) ? b[s + tid] : 0.f;
    }
    __syncthreads();

    // ---- Phase A: coupling dots (x_i . U), direct coalesced loads ----
    {
        const int colb = lane * 4;
        float4 vcA = make_float4(0.f,0.f,0.f,0.f), vsA = make_float4(0.f,0.f,0.f,0.f);
        if (colb < n) {
            const float* Xw = At + (size_t)(w * 64) * NCOL + s + colb;
            #pragma unroll 8
            for (int r = 0; r < 64; r++) {
                float uc = Ucm[w * 64 + r], us = Usm[w * 64 + r];
                float4 xv = *(const float4*)(Xw + (size_t)r * NCOL);
                vcA.x = fmaf(uc, xv.x, vcA.x); vcA.y = fmaf(uc, xv.y, vcA.y);
                vcA.z = fmaf(uc, xv.z, vcA.z); vcA.w = fmaf(uc, xv.w, vcA.w);
                vsA.x = fmaf(us, xv.x, vsA.x); vsA.y = fmaf(us, xv.y, vsA.y);
                vsA.z = fmaf(us, xv.z, vsA.z); vsA.w = fmaf(us, xv.w, vsA.w);
            }
        }
        *(float4*)&pAc[w][colb] = vcA;
        *(float4*)&pAs[w][colb] = vsA;
    }

    // ---- stage local Gram S into dsm (independent of phase A) ----
    {
        const float4* Sg = (const float4*)(g_Sall + (size_t)k * BLK * BLK);
        float4* Ss = (float4*)dsm;
        #pragma unroll
        for (int ii = 0; ii < 8; ii++) Ss[tid + 512 * ii] = Sg[tid + 512 * ii];
    }
    if (tid < BLK) tq[tid] = zz[tid] * yco[tid];
    __syncthreads();

    // ---- local strict-lower matvecs (both chains) ----
    {
        const int qq = tid >> 7, i = tid & 127, jb = qq * 32;
        float lc = 0.f, ls = 0.f;
        #pragma unroll 8
        for (int j2 = 0; j2 < 32; j2++) {
            int j = jb + j2;
            if (j < i) {
                float sv = dsm[j * BLK + i];
                lc = fmaf(sv, yco[j], lc);
                ls = fmaf(sv, yso[j], ls);
            }
        }
        plc[qq][i] = lc; pls[qq][i] = ls;
    }
    if (tid < 32) {          // exclusive prefix of z*yc_old
        float v0 = tq[4*tid], v1 = tq[4*tid+1], v2 = tq[4*tid+2], v3 = tq[4*tid+3];
        float i0 = v0, i1 = i0 + v1, i2 = i1 + v2, i3 = i2 + v3;
        float run = i3;
        #pragma unroll
        for (int o = 1; o < 32; o <<= 1) {
            float u2 = __shfl_up_sync(0xffffffffu, run, o);
            if ((int)tid >= o) run += u2;
        }
        float ex = run - i3;
        pref[4*tid] = ex; pref[4*tid+1] = ex + i0;
        pref[4*tid+2] = ex + i1; pref[4*tid+3] = ex + i2;
    }
    __syncthreads();

    // ---- combine + Jacobi update ----
    if (tid < BLK) {
        const int i = tid;
        float cc = 0.f, cs = 0.f;
        #pragma unroll
        for (int pp = 0; pp < 16; pp++) { cc += pAc[pp][i]; cs += pAs[pp][i]; }
        float lc = plc[0][i] + plc[1][i] + plc[2][i] + plc[3][i];
        float ls = pls[0][i] + pls[1][i] + pls[2][i] + pls[3][i];
        float zp = sPz + pref[i];
        float rc = (s + i == 0) ? 1.0f : 0.0f;
        float cnew = rc - EPS * (cc + lc - zz[i] * zp);
        float rs = fmaf(2.0f * g_T0, cnew * cnew, -2.0f * bb[i]);
        if (s + i == 0) rs += 2.0f * g_q0;
        float snew = rs - EPS * (cs + ls);
        ycn[i] = cnew; ysn[i] = snew;
        g_y[0][k * BLK + i] = cnew;
        g_y[1][k * BLK + i] = snew;
        if (last && i < n) out[s + i] = fmaf(0.5f, snew, bb[i]);
        tq[i] = zz[i] * cnew;
    }
    __syncthreads();

    if (last) return;

    if (tid < 32) {           // pz block sum of z*cnew, publish + segment delta
        float v = tq[4*tid] + tq[4*tid+1] + tq[4*tid+2] + tq[4*tid+3];
        #pragma unroll
        for (int o = 16; o; o >>= 1) v += __shfl_down_sync(0xffffffffu, v, o);
        if (tid == 0) {
            float old = g_pzh[p][k];
            g_pzh[p][k] = v;
            atomicAdd(&g_Wz[pr][seg], v - old);
        }
    }

    // ---- Phase U: u = X @ ynew; 8-lane groups per row, coalesced 128B chunks ----
    {
        const int g8 = lane >> 3, gl = lane & 7;     // 4 groups of 8 lanes
        for (int pass = 0; pass < 16; pass++) {
            int r = w * 64 + pass * 4 + g8;
            const float* rp = At + (size_t)r * NCOL + s;
            float uc = 0.f, us = 0.f;
            #pragma unroll
            for (int it = 0; it < 4; it++) {
                int col = it * 32 + gl * 4;
                if (col < n) {
                    float4 xv = *(const float4*)(rp + col);
                    uc = fmaf(xv.x, ycn[col],   fmaf(xv.y, ycn[col+1],
                         fmaf(xv.z, ycn[col+2], fmaf(xv.w, ycn[col+3], uc))));
                    us = fmaf(xv.x, ysn[col],   fmaf(xv.y, ysn[col+1],
                         fmaf(xv.z, ysn[col+2], fmaf(xv.w, ysn[col+3], us))));
                }
            }
            #pragma unroll
            for (int o = 4; o; o >>= 1) {
                uc += __shfl_down_sync(0xffffffffu, uc, o, 8);
                us += __shfl_down_sync(0xffffffffu, us, o, 8);
            }
            if (gl == 0) {
                float oc = g_uh[p][0][k][r], os = g_uh[p][1][k][r];
                g_uh[p][0][k][r] = uc;
                g_uh[p][1][k][r] = us;
                atomicAdd(&g_W[pr][0][seg][r], uc - oc);
                atomicAdd(&g_W[pr][1][seg][r], us - os);
            }
        }
    }
}

// ---------------- launch ----------------
extern "C" void kernel_launch(void* const* d_in, const int* in_sizes, int n_in,
                              void* d_out, int out_size) {
    const float* At = (const float*)d_in[0];
    const float* b  = (const float*)d_in[1];
    const float* w1 = (const float*)d_in[2];
    const float* W2 = (const float*)d_in[3];
    float* out = (float*)d_out;

    cudaFuncSetAttribute(big_kernel, cudaFuncAttributeMaxDynamicSharedMemorySize, BIGSM);

    init_kernel<<<1, 1024>>>(At, w1);
    t0_kernel<<<16, 256>>>(W2);
    if (out_size >= 2 * NCOL)
        copyb_kernel<<<(NCOL + 255) / 256, 256>>>(b, out);
    gram_kernel<<<NBLK, 512>>>(At);
    zero_state_kernel<<<160, 1024>>>();

    for (int t = 0; t < NIT; t++)
        big_kernel<<<NBLK, 512, BIGSM>>>(At, b, out, t & 1, t == NIT - 1 ? 1 : 0);
}

// round 8
// speedup vs baseline: 5.8900x; 1.5451x over previous
#include <cuda_runtime.h>

#define D      1024
#define NCOL   20000
#define TWO_M  512
#define DM1    1023
#define BLK    128
#define NBLK   157
#define FETA   1e-5f
#define EPS    (2.0f * FETA)
#define NIT    5
#define NSEG   8
#define SEGW   20
#define BIGSM  (BLK * BLK * (int)sizeof(float))   // 65536 B (S tile)

// ---------------- device globals (no allocation allowed) ----------------
__device__ __align__(16) float g_Spart[2][(size_t)NBLK * BLK * BLK];  // K-half partials
__device__ __align__(16) float g_uh[2][2][NBLK][D];   // [slot][chain][blk][row]
__device__ __align__(16) float g_W[2][2][NSEG][D];    // [slot][chain][seg][row]
__device__ float g_pzh[2][NBLK];
__device__ float g_Wz[2][NSEG];
__device__ __align__(16) float g_y[2][NBLK * BLK];
__device__ float g_x0[D];
__device__ float g_T0, g_q0;

// ---------------- init: x0 gather, q0 = w1.x0, zero T0 ----------------
__global__ __launch_bounds__(1024) void init_kernel(const float* __restrict__ At,
                                                    const float* __restrict__ w1) {
    __shared__ float red[32];
    int tid = threadIdx.x;
    float x0 = At[(size_t)tid * NCOL];
    g_x0[tid] = x0;
    float p = w1[tid] * x0;
    #pragma unroll
    for (int o = 16; o; o >>= 1) p += __shfl_down_sync(0xffffffffu, p, o);
    if ((tid & 31) == 0) red[tid >> 5] = p;
    __syncthreads();
    if (tid < 32) {
        float q = red[tid];
        #pragma unroll
        for (int o = 16; o; o >>= 1) q += __shfl_down_sync(0xffffffffu, q, o);
        if (tid == 0) { g_q0 = q; g_T0 = 0.0f; }
    }
}

// ---------------- T0 = ||W2_init @ a_0||^2 ; grid 16 ----------------
__global__ __launch_bounds__(256) void t0_kernel(const float* __restrict__ W2) {
    int wid = threadIdx.x >> 5, lane = threadIdx.x & 31;
    float acc = 0.0f;
    #pragma unroll
    for (int rr = 0; rr < 4; rr++) {
        int m = blockIdx.x * 32 + wid * 4 + rr;
        const float* row = W2 + (size_t)m * DM1;
        float p = 0.0f;
        for (int c = lane; c < DM1; c += 32) p = fmaf(row[c], g_x0[c], p);
        #pragma unroll
        for (int o = 16; o; o >>= 1) p += __shfl_down_sync(0xffffffffu, p, o);
        if (lane == 0) acc = fmaf(p, p, acc);
    }
    if (lane == 0) atomicAdd(&g_T0, acc);
}

// ---------------- copy b into out[N..2N) ----------------
__global__ void copyb_kernel(const float* __restrict__ b, float* __restrict__ out) {
    int i = blockIdx.x * blockDim.x + threadIdx.x;
    if (i < NCOL) out[NCOL + i] = b[i];
}

// ---------------- zero iteration state (both parities) ----------------
__global__ void zero_state_kernel() {
    int idx = blockIdx.x * blockDim.x + threadIdx.x;
    int stride = gridDim.x * blockDim.x;
    float* u = &g_uh[0][0][0][0];
    for (int i = idx; i < 2 * 2 * NBLK * D; i += stride) u[i] = 0.0f;
    float* w = &g_W[0][0][0][0];
    for (int i = idx; i < 2 * 2 * NSEG * D; i += stride) w[i] = 0.0f;
    float* y = &g_y[0][0];
    for (int i = idx; i < 2 * NBLK * BLK; i += stride) y[i] = 0.0f;
    if (idx < 2 * NBLK) (&g_pzh[0][0])[idx] = 0.0f;
    if (idx < 2 * NSEG) (&g_Wz[0][0])[idx] = 0.0f;
}

// ---------------- diag Gram partials; grid (157,2), 256 thr, 8x8 tiles ----------------
__global__ __launch_bounds__(256) void gram_kernel(const float* __restrict__ At) {
    __shared__ float sh[32][BLK];
    int k = blockIdx.x, s = k * BLK, kh = blockIdx.y, tid = threadIdx.x;
    int ty = tid >> 4, tx = tid & 15;
    float acc[8][8];
    #pragma unroll
    for (int i = 0; i < 8; i++)
        #pragma unroll
        for (int j = 0; j < 8; j++) acc[i][j] = 0.0f;

    for (int kt = 0; kt < 16; kt++) {
        int r0 = kh * 512 + kt * 32;
        #pragma unroll
        for (int i = 0; i < 4; i++) {
            int f = tid + 256 * i;
            int r = f >> 5;
            int c4 = (f & 31) * 4;
            float4 v = make_float4(0.f, 0.f, 0.f, 0.f);
            if (s + c4 + 3 < NCOL)
                v = *(const float4*)(At + (size_t)(r0 + r) * NCOL + s + c4);
            *(float4*)&sh[r][c4] = v;
        }
        __syncthreads();
        #pragma unroll 4
        for (int r2 = 0; r2 < 32; r2++) {
            float4 a4 = *(const float4*)&sh[r2][8 * ty];
            float4 a5 = *(const float4*)&sh[r2][8 * ty + 4];
            float4 b4 = *(const float4*)&sh[r2][8 * tx];
            float4 b5 = *(const float4*)&sh[r2][8 * tx + 4];
            float av[8] = {a4.x,a4.y,a4.z,a4.w,a5.x,a5.y,a5.z,a5.w};
            float bv[8] = {b4.x,b4.y,b4.z,b4.w,b5.x,b5.y,b5.z,b5.w};
            #pragma unroll
            for (int i = 0; i < 8; i++)
                #pragma unroll
                for (int j = 0; j < 8; j++) acc[i][j] = fmaf(av[i], bv[j], acc[i][j]);
        }
        __syncthreads();
    }
    float* Sk = g_Spart[kh] + (size_t)k * BLK * BLK;
    #pragma unroll
    for (int i = 0; i < 8; i++)
        #pragma unroll
        for (int j = 0; j < 8; j++)
            Sk[(8 * ty + i) * BLK + (8 * tx + j)] = acc[i][j];
}

// ---------------- one fused Jacobi sweep: 157 CTAs, all blocks parallel ----------------
// parity p: reads W[p], u[p^1], pz[p], Wz[p]; writes u[p], pz[p], W[p^1], Wz[p^1]
__global__ __launch_bounds__(512) void big_kernel(const float* __restrict__ At,
                                                  const float* __restrict__ b,
                                                  float* __restrict__ out,
                                                  int p, int last) {
    extern __shared__ float dsm[];                 // S tile (128x128)
    __shared__ float Ucm[D], Usm[D];
    __shared__ float pAc[16][BLK], pAs[16][BLK];
    __shared__ float plc[4][BLK], pls[4][BLK];
    __shared__ float yco[BLK], yso[BLK], ycn[BLK], ysn[BLK];
    __shared__ float zz[BLK], bb[BLK], tq[BLK], pref[BLK];
    __shared__ float sPz;

    const int tid = threadIdx.x;
    const int w = tid >> 5, lane = tid & 31;
    const int k = blockIdx.x;
    const int s = k * BLK;
    const int n = (NCOL - s < BLK) ? (NCOL - s) : BLK;
    const int seg = k / SEGW;
    const int segbase = seg * SEGW;
    const int pr = p ^ 1;

    // ---- build exclusive-prefix coupling vectors (float4 path) ----
    {
        const int chain = tid >> 8;       // 0 = c, 1 = sg
        const int slot = tid & 255;       // float4 slot within 1024-float vector
        const float4* Wp = (const float4*)&g_W[p][chain][0][0];
        const float4* up = (const float4*)&g_uh[pr][chain][0][0];
        float4 acc = make_float4(0.f, 0.f, 0.f, 0.f);
        #pragma unroll 2
        for (int s2 = 0; s2 < seg; s2++) {
            float4 v = Wp[s2 * 256 + slot];
            acc.x += v.x; acc.y += v.y; acc.z += v.z; acc.w += v.w;
        }
        #pragma unroll 4
        for (int k2 = segbase; k2 < k; k2++) {
            float4 v = up[k2 * 256 + slot];
            acc.x += v.x; acc.y += v.y; acc.z += v.z; acc.w += v.w;
        }
        float4* dst = (float4*)(chain ? Usm : Ucm);
        dst[slot] = acc;
    }
    if (tid == 0) {
        float a = 0.f;
        for (int s2 = 0; s2 < seg; s2++) a += g_Wz[p][s2];
        for (int k2 = segbase; k2 < k; k2++) a += g_pzh[pr][k2];
        sPz = a;
    }
    if (tid < BLK) {
        yco[tid] = g_y[0][k * BLK + tid];
        yso[tid] = g_y[1][k * BLK + tid];
        zz[tid] = (tid < n) ? At[(size_t)DM1 * NCOL + s + tid] : 0.f;
        bb[tid] = (tid < n) ? b[s + tid] : 0.f;
    }
    __syncthreads();

    // ---- Phase A: coupling dots (x_i . U), direct coalesced loads ----
    {
        const int colb = lane * 4;
        float4 vcA = make_float4(0.f,0.f,0.f,0.f), vsA = make_float4(0.f,0.f,0.f,0.f);
        if (colb < n) {
            const float* Xw = At + (size_t)(w * 64) * NCOL + s + colb;
            #pragma unroll 8
            for (int r = 0; r < 64; r++) {
                float uc = Ucm[w * 64 + r], us = Usm[w * 64 + r];
                float4 xv = *(const float4*)(Xw + (size_t)r * NCOL);
                vcA.x = fmaf(uc, xv.x, vcA.x); vcA.y = fmaf(uc, xv.y, vcA.y);
                vcA.z = fmaf(uc, xv.z, vcA.z); vcA.w = fmaf(uc, xv.w, vcA.w);
                vsA.x = fmaf(us, xv.x, vsA.x); vsA.y = fmaf(us, xv.y, vsA.y);
                vsA.z = fmaf(us, xv.z, vsA.z); vsA.w = fmaf(us, xv.w, vsA.w);
            }
        }
        *(float4*)&pAc[w][colb] = vcA;
        *(float4*)&pAs[w][colb] = vsA;
    }

    // ---- stage local Gram S = sum of K-half partials (independent of phase A) ----
    {
        const float4* Sg0 = (const float4*)(g_Spart[0] + (size_t)k * BLK * BLK);
        const float4* Sg1 = (const float4*)(g_Spart[1] + (size_t)k * BLK * BLK);
        float4* Ss = (float4*)dsm;
        #pragma unroll
        for (int ii = 0; ii < 8; ii++) {
            float4 a = Sg0[tid + 512 * ii];
            float4 c = Sg1[tid + 512 * ii];
            Ss[tid + 512 * ii] = make_float4(a.x + c.x, a.y + c.y, a.z + c.z, a.w + c.w);
        }
    }
    if (tid < BLK) tq[tid] = zz[tid] * yco[tid];
    __syncthreads();

    // ---- local strict-lower matvecs (both chains) ----
    {
        const int qq = tid >> 7, i = tid & 127, jb = qq * 32;
        float lc = 0.f, ls = 0.f;
        #pragma unroll 8
        for (int j2 = 0; j2 < 32; j2++) {
            int j = jb + j2;
            if (j < i) {
                float sv = dsm[j * BLK + i];
                lc = fmaf(sv, yco[j], lc);
                ls = fmaf(sv, yso[j], ls);
            }
        }
        plc[qq][i] = lc; pls[qq][i] = ls;
    }
    if (tid < 32) {          // exclusive prefix of z*yc_old
        float v0 = tq[4*tid], v1 = tq[4*tid+1], v2 = tq[4*tid+2], v3 = tq[4*tid+3];
        float i0 = v0, i1 = i0 + v1, i2 = i1 + v2, i3 = i2 + v3;
        float run = i3;
        #pragma unroll
        for (int o = 1; o < 32; o <<= 1) {
            float u2 = __shfl_up_sync(0xffffffffu, run, o);
            if ((int)tid >= o) run += u2;
        }
        float ex = run - i3;
        pref[4*tid] = ex; pref[4*tid+1] = ex + i0;
        pref[4*tid+2] = ex + i1; pref[4*tid+3] = ex + i2;
    }
    __syncthreads();

    // ---- combine + Jacobi update ----
    if (tid < BLK) {
        const int i = tid;
        float cc = 0.f, cs = 0.f;
        #pragma unroll
        for (int pp = 0; pp < 16; pp++) { cc += pAc[pp][i]; cs += pAs[pp][i]; }
        float lc = plc[0][i] + plc[1][i] + plc[2][i] + plc[3][i];
        float ls = pls[0][i] + pls[1][i] + pls[2][i] + pls[3][i];
        float zp = sPz + pref[i];
        float rc = (s + i == 0) ? 1.0f : 0.0f;
        float cnew = rc - EPS * (cc + lc - zz[i] * zp);
        float rs = fmaf(2.0f * g_T0, cnew * cnew, -2.0f * bb[i]);
        if (s + i == 0) rs += 2.0f * g_q0;
        float snew = rs - EPS * (cs + ls);
        ycn[i] = cnew; ysn[i] = snew;
        g_y[0][k * BLK + i] = cnew;
        g_y[1][k * BLK + i] = snew;
        if (last && i < n) out[s + i] = fmaf(0.5f, snew, bb[i]);
        tq[i] = zz[i] * cnew;
    }
    __syncthreads();

    if (last) return;

    if (tid < 32) {           // pz block sum of z*cnew, publish + segment delta
        float v = tq[4*tid] + tq[4*tid+1] + tq[4*tid+2] + tq[4*tid+3];
        #pragma unroll
        for (int o = 16; o; o >>= 1) v += __shfl_down_sync(0xffffffffu, v, o);
        if (tid == 0) {
            float old = g_pzh[p][k];
            g_pzh[p][k] = v;
            atomicAdd(&g_Wz[pr][seg], v - old);
        }
    }

    // ---- Phase U: u = X @ ynew; 8-lane groups per row, coalesced 128B chunks ----
    {
        const int g8 = lane >> 3, gl = lane & 7;     // 4 groups of 8 lanes
        for (int pass = 0; pass < 16; pass++) {
            int r = w * 64 + pass * 4 + g8;
            const float* rp = At + (size_t)r * NCOL + s;
            float uc = 0.f, us = 0.f;
            #pragma unroll
            for (int it = 0; it < 4; it++) {
                int col = it * 32 + gl * 4;
                if (col < n) {
                    float4 xv = *(const float4*)(rp + col);
                    uc = fmaf(xv.x, ycn[col],   fmaf(xv.y, ycn[col+1],
                         fmaf(xv.z, ycn[col+2], fmaf(xv.w, ycn[col+3], uc))));
                    us = fmaf(xv.x, ysn[col],   fmaf(xv.y, ysn[col+1],
                         fmaf(xv.z, ysn[col+2], fmaf(xv.w, ysn[col+3], us))));
                }
            }
            #pragma unroll
            for (int o = 4; o; o >>= 1) {
                uc += __shfl_down_sync(0xffffffffu, uc, o, 8);
                us += __shfl_down_sync(0xffffffffu, us, o, 8);
            }
            if (gl == 0) {
                float oc = g_uh[p][0][k][r], os = g_uh[p][1][k][r];
                g_uh[p][0][k][r] = uc;
                g_uh[p][1][k][r] = us;
                atomicAdd(&g_W[pr][0][seg][r], uc - oc);
                atomicAdd(&g_W[pr][1][seg][r], us - os);
            }
        }
    }
}

// ---------------- launch ----------------
extern "C" void kernel_launch(void* const* d_in, const int* in_sizes, int n_in,
                              void* d_out, int out_size) {
    const float* At = (const float*)d_in[0];
    const float* b  = (const float*)d_in[1];
    const float* w1 = (const float*)d_in[2];
    const float* W2 = (const float*)d_in[3];
    float* out = (float*)d_out;

    cudaFuncSetAttribute(big_kernel, cudaFuncAttributeMaxDynamicSharedMemorySize, BIGSM);

    init_kernel<<<1, 1024>>>(At, w1);
    t0_kernel<<<16, 256>>>(W2);
    if (out_size >= 2 * NCOL)
        copyb_kernel<<<(NCOL + 255) / 256, 256>>>(b, out);
    gram_kernel<<<dim3(NBLK, 2), 256>>>(At);
    zero_state_kernel<<<160, 1024>>>();

    for (int t = 0; t < NIT; t++)
        big_kernel<<<NBLK, 512, BIGSM>>>(At, b, out, t & 1, t == NIT - 1 ? 1 : 0);
}

// round 9
// speedup vs baseline: 7.9600x; 1.3514x over previous
#include <cuda_runtime.h>

#define D      1024
#define NCOL   20000
#define TWO_M  512
#define DM1    1023
#define BLK    128
#define NBLK   157
#define FETA   1e-5f
#define EPS    (2.0f * FETA)
#define NIT    5
#define NSEG   8
#define SEGW   20
#define BIGSM  (BLK * BLK * (int)sizeof(float))   // 65536 B (S tile)

// ---------------- device globals (no allocation allowed) ----------------
__device__ __align__(16) float g_Spart[2][(size_t)NBLK * BLK * BLK];  // K-half partials
__device__ __align__(16) float g_uh[2][2][NBLK][D];   // [slot][chain][blk][row]
__device__ __align__(16) float g_W[2][2][NSEG][D];    // [slot][chain][seg][row]
__device__ float g_pzh[2][NBLK];
__device__ float g_Wz[2][NSEG];
__device__ __align__(16) float g_y[2][NBLK * BLK];
__device__ float g_x0[D];
__device__ float g_T0, g_q0;

// ---------------- init: x0 gather, q0 = w1.x0, zero T0 ----------------
__global__ __launch_bounds__(1024) void init_kernel(const float* __restrict__ At,
                                                    const float* __restrict__ w1) {
    __shared__ float red[32];
    int tid = threadIdx.x;
    float x0 = At[(size_t)tid * NCOL];
    g_x0[tid] = x0;
    float p = w1[tid] * x0;
    #pragma unroll
    for (int o = 16; o; o >>= 1) p += __shfl_down_sync(0xffffffffu, p, o);
    if ((tid & 31) == 0) red[tid >> 5] = p;
    __syncthreads();
    if (tid < 32) {
        float q = red[tid];
        #pragma unroll
        for (int o = 16; o; o >>= 1) q += __shfl_down_sync(0xffffffffu, q, o);
        if (tid == 0) { g_q0 = q; g_T0 = 0.0f; }
    }
}

// ---------------- T0 = ||W2_init @ a_0||^2 ; grid 16 ----------------
__global__ __launch_bounds__(256) void t0_kernel(const float* __restrict__ W2) {
    int wid = threadIdx.x >> 5, lane = threadIdx.x & 31;
    float acc = 0.0f;
    #pragma unroll
    for (int rr = 0; rr < 4; rr++) {
        int m = blockIdx.x * 32 + wid * 4 + rr;
        const float* row = W2 + (size_t)m * DM1;
        float p = 0.0f;
        for (int c = lane; c < DM1; c += 32) p = fmaf(row[c], g_x0[c], p);
        #pragma unroll
        for (int o = 16; o; o >>= 1) p += __shfl_down_sync(0xffffffffu, p, o);
        if (lane == 0) acc = fmaf(p, p, acc);
    }
    if (lane == 0) atomicAdd(&g_T0, acc);
}

// ---------------- copy b into out[N..2N) ----------------
__global__ void copyb_kernel(const float* __restrict__ b, float* __restrict__ out) {
    int i = blockIdx.x * blockDim.x + threadIdx.x;
    if (i < NCOL) out[NCOL + i] = b[i];
}

// ---------------- zero iteration state (both parities) ----------------
__global__ void zero_state_kernel() {
    int idx = blockIdx.x * blockDim.x + threadIdx.x;
    int stride = gridDim.x * blockDim.x;
    float* u = &g_uh[0][0][0][0];
    for (int i = idx; i < 2 * 2 * NBLK * D; i += stride) u[i] = 0.0f;
    float* w = &g_W[0][0][0][0];
    for (int i = idx; i < 2 * 2 * NSEG * D; i += stride) w[i] = 0.0f;
    float* y = &g_y[0][0];
    for (int i = idx; i < 2 * NBLK * BLK; i += stride) y[i] = 0.0f;
    if (idx < 2 * NBLK) (&g_pzh[0][0])[idx] = 0.0f;
    if (idx < 2 * NSEG) (&g_Wz[0][0])[idx] = 0.0f;
}

// ---------------- diag Gram partials; UPPER-TRIANGLE tiles only ----------------
// grid (157,2), 256 thr. 136 tiles (8x8) mapped densely to threads 0..135;
// warps 5..7 idle through compute. Lower triangle of S is never read downstream.
__global__ __launch_bounds__(256) void gram_kernel(const float* __restrict__ At) {
    __shared__ float sh[32][BLK];
    int k = blockIdx.x, s = k * BLK, kh = blockIdx.y, tid = threadIdx.x;

    // decode tile (ti, tj), tj >= ti, from dense index tid in [0,136)
    int ti = 0, tj = 0;
    {
        int rem = tid;
        #pragma unroll
        for (int i = 0; i < 16; i++) {
            if (rem >= 16 - i) rem -= 16 - i; else { if (ti == 0 || true) {} }
        }
    }
    {   // (redo decode simply; compiler folds)
        int rem = tid, i = 0;
        while (i < 16 && rem >= 16 - i) { rem -= 16 - i; i++; }
        ti = i; tj = i + rem;
    }
    const bool active = (tid < 136);

    float acc[8][8];
    #pragma unroll
    for (int i = 0; i < 8; i++)
        #pragma unroll
        for (int j = 0; j < 8; j++) acc[i][j] = 0.0f;

    for (int kt = 0; kt < 16; kt++) {
        int r0 = kh * 512 + kt * 32;
        #pragma unroll
        for (int i = 0; i < 4; i++) {
            int f = tid + 256 * i;
            int r = f >> 5;
            int c4 = (f & 31) * 4;
            float4 v = make_float4(0.f, 0.f, 0.f, 0.f);
            if (s + c4 + 3 < NCOL)
                v = *(const float4*)(At + (size_t)(r0 + r) * NCOL + s + c4);
            *(float4*)&sh[r][c4] = v;
        }
        __syncthreads();
        if (active) {
            #pragma unroll 4
            for (int r2 = 0; r2 < 32; r2++) {
                float4 a4 = *(const float4*)&sh[r2][8 * ti];
                float4 a5 = *(const float4*)&sh[r2][8 * ti + 4];
                float4 b4 = *(const float4*)&sh[r2][8 * tj];
                float4 b5 = *(const float4*)&sh[r2][8 * tj + 4];
                float av[8] = {a4.x,a4.y,a4.z,a4.w,a5.x,a5.y,a5.z,a5.w};
                float bv[8] = {b4.x,b4.y,b4.z,b4.w,b5.x,b5.y,b5.z,b5.w};
                #pragma unroll
                for (int i = 0; i < 8; i++)
                    #pragma unroll
                    for (int j = 0; j < 8; j++) acc[i][j] = fmaf(av[i], bv[j], acc[i][j]);
            }
        }
        __syncthreads();
    }
    if (active) {
        float* Sk = g_Spart[kh] + (size_t)k * BLK * BLK;
        #pragma unroll
        for (int i = 0; i < 8; i++) {
            int row = 8 * ti + i;
            *(float4*)&Sk[row * BLK + 8 * tj]     = make_float4(acc[i][0], acc[i][1], acc[i][2], acc[i][3]);
            *(float4*)&Sk[row * BLK + 8 * tj + 4] = make_float4(acc[i][4], acc[i][5], acc[i][6], acc[i][7]);
        }
    }
}

// ---------------- one fused Jacobi sweep: 157 CTAs, all blocks parallel ----------------
// parity p: reads W[p], u[p^1], pz[p], Wz[p]; writes u[p], pz[p], W[p^1], Wz[p^1]
// first=1: y==0 state -> skip prefix-build / phase A / S-stage / local matvec
__global__ __launch_bounds__(512) void big_kernel(const float* __restrict__ At,
                                                  const float* __restrict__ b,
                                                  float* __restrict__ out,
                                                  int p, int first, int last) {
    extern __shared__ float dsm[];                 // S tile (128x128)
    __shared__ float Ucm[D], Usm[D];
    __shared__ float pAc[16][BLK], pAs[16][BLK];
    __shared__ float plc[4][BLK], pls[4][BLK];
    __shared__ float yco[BLK], yso[BLK], ycn[BLK], ysn[BLK];
    __shared__ float zz[BLK], bb[BLK], tq[BLK], pref[BLK];
    __shared__ float sPz;

    const int tid = threadIdx.x;
    const int w = tid >> 5, lane = tid & 31;
    const int k = blockIdx.x;
    const int s = k * BLK;
    const int n = (NCOL - s < BLK) ? (NCOL - s) : BLK;
    const int seg = k / SEGW;
    const int segbase = seg * SEGW;
    const int pr = p ^ 1;

    if (tid < BLK) {
        zz[tid] = (tid < n) ? At[(size_t)DM1 * NCOL + s + tid] : 0.f;
        bb[tid] = (tid < n) ? b[s + tid] : 0.f;
    }

    if (!first) {
        // ---- build exclusive-prefix coupling vectors (float4 path) ----
        {
            const int chain = tid >> 8;
            const int slot = tid & 255;
            const float4* Wp = (const float4*)&g_W[p][chain][0][0];
            const float4* up = (const float4*)&g_uh[pr][chain][0][0];
            float4 acc = make_float4(0.f, 0.f, 0.f, 0.f);
            #pragma unroll 2
            for (int s2 = 0; s2 < seg; s2++) {
                float4 v = Wp[s2 * 256 + slot];
                acc.x += v.x; acc.y += v.y; acc.z += v.z; acc.w += v.w;
            }
            #pragma unroll 4
            for (int k2 = segbase; k2 < k; k2++) {
                float4 v = up[k2 * 256 + slot];
                acc.x += v.x; acc.y += v.y; acc.z += v.z; acc.w += v.w;
            }
            float4* dst = (float4*)(chain ? Usm : Ucm);
            dst[slot] = acc;
        }
        if (tid == 0) {
            float a = 0.f;
            for (int s2 = 0; s2 < seg; s2++) a += g_Wz[p][s2];
            for (int k2 = segbase; k2 < k; k2++) a += g_pzh[pr][k2];
            sPz = a;
        }
        if (tid < BLK) {
            yco[tid] = g_y[0][k * BLK + tid];
            yso[tid] = g_y[1][k * BLK + tid];
        }
        __syncthreads();

        // ---- Phase A: coupling dots (x_i . U), direct coalesced loads ----
        {
            const int colb = lane * 4;
            float4 vcA = make_float4(0.f,0.f,0.f,0.f), vsA = make_float4(0.f,0.f,0.f,0.f);
            if (colb < n) {
                const float* Xw = At + (size_t)(w * 64) * NCOL + s + colb;
                #pragma unroll 8
                for (int r = 0; r < 64; r++) {
                    float uc = Ucm[w * 64 + r], us = Usm[w * 64 + r];
                    float4 xv = *(const float4*)(Xw + (size_t)r * NCOL);
                    vcA.x = fmaf(uc, xv.x, vcA.x); vcA.y = fmaf(uc, xv.y, vcA.y);
                    vcA.z = fmaf(uc, xv.z, vcA.z); vcA.w = fmaf(uc, xv.w, vcA.w);
                    vsA.x = fmaf(us, xv.x, vsA.x); vsA.y = fmaf(us, xv.y, vsA.y);
                    vsA.z = fmaf(us, xv.z, vsA.z); vsA.w = fmaf(us, xv.w, vsA.w);
                }
            }
            *(float4*)&pAc[w][colb] = vcA;
            *(float4*)&pAs[w][colb] = vsA;
        }

        // ---- stage local Gram S = sum of K-half partials ----
        {
            const float4* Sg0 = (const float4*)(g_Spart[0] + (size_t)k * BLK * BLK);
            const float4* Sg1 = (const float4*)(g_Spart[1] + (size_t)k * BLK * BLK);
            float4* Ss = (float4*)dsm;
            #pragma unroll
            for (int ii = 0; ii < 8; ii++) {
                float4 a = Sg0[tid + 512 * ii];
                float4 c = Sg1[tid + 512 * ii];
                Ss[tid + 512 * ii] = make_float4(a.x + c.x, a.y + c.y, a.z + c.z, a.w + c.w);
            }
        }
        if (tid < BLK) tq[tid] = zz[tid] * yco[tid];
        __syncthreads();

        // ---- local strict-lower matvecs (both chains; reads upper triangle of S) ----
        {
            const int qq = tid >> 7, i = tid & 127, jb = qq * 32;
            float lc = 0.f, ls = 0.f;
            #pragma unroll 8
            for (int j2 = 0; j2 < 32; j2++) {
                int j = jb + j2;
                if (j < i) {
                    float sv = dsm[j * BLK + i];
                    lc = fmaf(sv, yco[j], lc);
                    ls = fmaf(sv, yso[j], ls);
                }
            }
            plc[qq][i] = lc; pls[qq][i] = ls;
        }
        if (tid < 32) {          // exclusive prefix of z*yc_old
            float v0 = tq[4*tid], v1 = tq[4*tid+1], v2 = tq[4*tid+2], v3 = tq[4*tid+3];
            float i0 = v0, i1 = i0 + v1, i2 = i1 + v2, i3 = i2 + v3;
            float run = i3;
            #pragma unroll
            for (int o = 1; o < 32; o <<= 1) {
                float u2 = __shfl_up_sync(0xffffffffu, run, o);
                if ((int)tid >= o) run += u2;
            }
            float ex = run - i3;
            pref[4*tid] = ex; pref[4*tid+1] = ex + i0;
            pref[4*tid+2] = ex + i1; pref[4*tid+3] = ex + i2;
        }
        __syncthreads();
    }

    // ---- combine + Jacobi update ----
    if (tid < BLK) {
        const int i = tid;
        float cc = 0.f, cs = 0.f, lc = 0.f, ls = 0.f, zp = 0.f;
        if (!first) {
            #pragma unroll
            for (int pp = 0; pp < 16; pp++) { cc += pAc[pp][i]; cs += pAs[pp][i]; }
            lc = plc[0][i] + plc[1][i] + plc[2][i] + plc[3][i];
            ls = pls[0][i] + pls[1][i] + pls[2][i] + pls[3][i];
            zp = sPz + pref[i];
        }
        float rc = (s + i == 0) ? 1.0f : 0.0f;
        float cnew = rc - EPS * (cc + lc - zz[i] * zp);
        float rs = fmaf(2.0f * g_T0, cnew * cnew, -2.0f * bb[i]);
        if (s + i == 0) rs += 2.0f * g_q0;
        float snew = rs - EPS * (cs + ls);
        ycn[i] = cnew; ysn[i] = snew;
        g_y[0][k * BLK + i] = cnew;
        g_y[1][k * BLK + i] = snew;
        if (last && i < n) out[s + i] = fmaf(0.5f, snew, bb[i]);
        tq[i] = zz[i] * cnew;
    }
    __syncthreads();

    if (last) return;

    if (tid < 32) {           // pz block sum of z*cnew, publish + segment delta
        float v = tq[4*tid] + tq[4*tid+1] + tq[4*tid+2] + tq[4*tid+3];
        #pragma unroll
        for (int o = 16; o; o >>= 1) v += __shfl_down_sync(0xffffffffu, v, o);
        if (tid == 0) {
            float old = g_pzh[p][k];
            g_pzh[p][k] = v;
            atomicAdd(&g_Wz[pr][seg], v - old);
        }
    }

    // ---- Phase U: u = X @ ynew; pass pairs fused for MLP 8 ----
    {
        const int g8 = lane >> 3, gl = lane & 7;     // 4 groups of 8 lanes
        for (int m = 0; m < 8; m++) {
            int r0 = w * 64 + m * 8 + g8;
            int r1 = r0 + 4;
            const float* rp0 = At + (size_t)r0 * NCOL + s;
            const float* rp1 = At + (size_t)r1 * NCOL + s;
            float uc0 = 0.f, us0 = 0.f, uc1 = 0.f, us1 = 0.f;
            #pragma unroll
            for (int it = 0; it < 4; it++) {
                int col = it * 32 + gl * 4;
                if (col < n) {
                    float4 xa = *(const float4*)(rp0 + col);
                    float4 xb = *(const float4*)(rp1 + col);
                    float y0 = ycn[col], y1 = ycn[col+1], y2 = ycn[col+2], y3 = ycn[col+3];
                    float t0 = ysn[col], t1 = ysn[col+1], t2 = ysn[col+2], t3 = ysn[col+3];
                    uc0 = fmaf(xa.x,y0,fmaf(xa.y,y1,fmaf(xa.z,y2,fmaf(xa.w,y3,uc0))));
                    us0 = fmaf(xa.x,t0,fmaf(xa.y,t1,fmaf(xa.z,t2,fmaf(xa.w,t3,us0))));
                    uc1 = fmaf(xb.x,y0,fmaf(xb.y,y1,fmaf(xb.z,y2,fmaf(xb.w,y3,uc1))));
                    us1 = fmaf(xb.x,t0,fmaf(xb.y,t1,fmaf(xb.z,t2,fmaf(xb.w,t3,us1))));
                }
            }
            #pragma unroll
            for (int o = 4; o; o >>= 1) {
                uc0 += __shfl_down_sync(0xffffffffu, uc0, o, 8);
                us0 += __shfl_down_sync(0xffffffffu, us0, o, 8);
                uc1 += __shfl_down_sync(0xffffffffu, uc1, o, 8);
                us1 += __shfl_down_sync(0xffffffffu, us1, o, 8);
            }
            if (gl == 0) {
                float oc0 = g_uh[p][0][k][r0], os0 = g_uh[p][1][k][r0];
                float oc1 = g_uh[p][0][k][r1], os1 = g_uh[p][1][k][r1];
                g_uh[p][0][k][r0] = uc0; g_uh[p][1][k][r0] = us0;
                g_uh[p][0][k][r1] = uc1; g_uh[p][1][k][r1] = us1;
                atomicAdd(&g_W[pr][0][seg][r0], uc0 - oc0);
                atomicAdd(&g_W[pr][1][seg][r0], us0 - os0);
                atomicAdd(&g_W[pr][0][seg][r1], uc1 - oc1);
                atomicAdd(&g_W[pr][1][seg][r1], us1 - os1);
            }
        }
    }
}

// ---------------- launch ----------------
extern "C" void kernel_launch(void* const* d_in, const int* in_sizes, int n_in,
                              void* d_out, int out_size) {
    const float* At = (const float*)d_in[0];
    const float* b  = (const float*)d_in[1];
    const float* w1 = (const float*)d_in[2];
    const float* W2 = (const float*)d_in[3];
    float* out = (float*)d_out;

    cudaFuncSetAttribute(big_kernel, cudaFuncAttributeMaxDynamicSharedMemorySize, BIGSM);

    init_kernel<<<1, 1024>>>(At, w1);
    t0_kernel<<<16, 256>>>(W2);
    if (out_size >= 2 * NCOL)
        copyb_kernel<<<(NCOL + 255) / 256, 256>>>(b, out);
    gram_kernel<<<dim3(NBLK, 2), 256>>>(At);
    zero_state_kernel<<<160, 1024>>>();

    for (int t = 0; t < NIT; t++)
        big_kernel<<<NBLK, 512, BIGSM>>>(At, b, out, t & 1,
                                         t == 0 ? 1 : 0, t == NIT - 1 ? 1 : 0);
}